// round 10
// baseline (speedup 1.0000x reference)
#include <cuda_runtime.h>
#include <cuda_bf16.h>
#include <cstdint>

#define N_NODES 100000
#define N_EDGES 500000
#define ET 3
#define C 128
#define NC (N_NODES * C)
#define LN_EPS 1e-5f
#define L2_EPS 1e-12f

#define PITCH 40                   // halves per smem row (bank-conflict-free)
#define CH (128 * PITCH)           // halves per 128x32 chunk plane
#define CB (CH * 2)                // bytes per plane (10240)

// ---------------- scratch (static device globals; no allocation) ----------------
__device__ float g_msg0[NC];
__device__ float g_msg1[NC];
__device__ float g_msg2[NC];
__device__ float g_accb[NC];
__device__ float g_h[NC];
__device__ __align__(16) __nv_bfloat16 g_xh[NC];
__device__ __align__(16) __nv_bfloat16 g_xl[NC];
__device__ __align__(16) __nv_bfloat16 g_ah[3 * NC];   // agg planes hi
__device__ __align__(16) __nv_bfloat16 g_al[3 * NC];   // agg planes lo
__device__ __align__(16) __nv_bfloat16 g_hh[NC];       // h planes
__device__ __align__(16) __nv_bfloat16 g_hl[NC];
__device__ __align__(16) __nv_bfloat16 g_wth[17 * C * C];  // transposed+split weights [n][k]
__device__ __align__(16) __nv_bfloat16 g_wtl[17 * C * C];
__device__ float g_wsum[2 * C * C];
__device__ float g_bsum[2 * C];
__device__ float g_invdeg[ET * N_NODES];
__device__ int g_cnt[ET * N_NODES];
__device__ int g_cur[ET * N_NODES];
__device__ int g_rowptr[ET * (N_NODES + 1)];
__device__ int g_col[ET * N_EDGES];
__device__ int g_bofs[ET * 128];

// ---------------- helpers ----------------
__device__ __forceinline__ uint32_t smem_u32(const void* p) {
    uint32_t a;
    asm("{ .reg .u64 t; cvta.to.shared.u64 t, %1; cvt.u32.u64 %0, t; }" : "=r"(a) : "l"(p));
    return a;
}
__device__ __forceinline__ void cp16(uint32_t dst, const void* src, int srcsize) {
    asm volatile("cp.async.cg.shared.global [%0], [%1], 16, %2;"
                 :: "r"(dst), "l"(src), "r"(srcsize));
}
#define CP_COMMIT() asm volatile("cp.async.commit_group;" ::: "memory")
#define CP_WAIT1()  asm volatile("cp.async.wait_group 1;" ::: "memory")
#define CP_WAIT0()  asm volatile("cp.async.wait_group 0;" ::: "memory")

__device__ __forceinline__ void split2(float x, __nv_bfloat16& hi, __nv_bfloat16& lo) {
    hi = __float2bfloat16_rn(x);
    lo = __float2bfloat16_rn(x - __bfloat162float(hi));
}
__device__ __forceinline__ void mma_bf16(float* d, const uint32_t* a, uint32_t b0, uint32_t b1) {
    asm volatile(
        "mma.sync.aligned.m16n8k16.row.col.f32.bf16.bf16.f32 "
        "{%0,%1,%2,%3}, {%4,%5,%6,%7}, {%8,%9}, {%0,%1,%2,%3};"
        : "+f"(d[0]), "+f"(d[1]), "+f"(d[2]), "+f"(d[3])
        : "r"(a[0]), "r"(a[1]), "r"(a[2]), "r"(a[3]), "r"(b0), "r"(b1));
}
__device__ __forceinline__ void ldsm4(uint32_t a, uint32_t& r0, uint32_t& r1,
                                      uint32_t& r2, uint32_t& r3) {
    asm volatile("ldmatrix.sync.aligned.m8n8.x4.shared.b16 {%0,%1,%2,%3}, [%4];"
                 : "=r"(r0), "=r"(r1), "=r"(r2), "=r"(r3) : "r"(a));
}

// ---------------- CSR build ----------------
__global__ void k_zero_int() {
    int i = blockIdx.x * blockDim.x + threadIdx.x;
    if (i < ET * N_NODES) { g_cnt[i] = 0; g_cur[i] = 0; }
}
__global__ void k_zero_acc() {
    int i = blockIdx.x * blockDim.x + threadIdx.x;
    if (i < NC) g_accb[i] = 0.f;
}
__global__ void k_hist(const int* __restrict__ edges) {
    int i = blockIdx.x * blockDim.x + threadIdx.x;
    if (i >= ET * N_EDGES) return;
    int t = i / N_EDGES, e = i - t * N_EDGES;
    int dst = edges[(t * 2 + 1) * N_EDGES + e];
    atomicAdd(&g_cnt[t * N_NODES + dst], 1);
}
__global__ void k_scan1() {
    int t = blockIdx.y;
    int i = blockIdx.x * 1024 + threadIdx.x;
    __shared__ int sm[1024];
    int v = (i < N_NODES) ? g_cnt[t * N_NODES + i] : 0;
    sm[threadIdx.x] = v;
    __syncthreads();
    for (int off = 1; off < 1024; off <<= 1) {
        int add = (threadIdx.x >= off) ? sm[threadIdx.x - off] : 0;
        __syncthreads();
        sm[threadIdx.x] += add;
        __syncthreads();
    }
    if (i < N_NODES) g_rowptr[t * (N_NODES + 1) + i] = sm[threadIdx.x] - v;
    if (threadIdx.x == 1023) g_bofs[t * 128 + blockIdx.x] = sm[1023];
}
__global__ void k_scan2() {
    int t = threadIdx.x;
    if (t >= ET) return;
    int nb = (N_NODES + 1023) / 1024;
    int run = 0;
    for (int b = 0; b < nb; b++) { int v = g_bofs[t * 128 + b]; g_bofs[t * 128 + b] = run; run += v; }
    g_rowptr[t * (N_NODES + 1) + N_NODES] = run;
}
__global__ void k_scan3() {
    int t = blockIdx.y;
    int i = blockIdx.x * 1024 + threadIdx.x;
    if (i < N_NODES) g_rowptr[t * (N_NODES + 1) + i] += g_bofs[t * 128 + blockIdx.x];
}
__global__ void k_invdeg() {
    int i = blockIdx.x * blockDim.x + threadIdx.x;
    if (i < ET * N_NODES) {
        int c = g_cnt[i];
        g_invdeg[i] = 1.0f / (float)(c > 1 ? c : 1);
    }
}
__global__ void k_scatter(const int* __restrict__ edges) {
    int i = blockIdx.x * blockDim.x + threadIdx.x;
    if (i >= ET * N_EDGES) return;
    int t = i / N_EDGES, e = i - t * N_EDGES;
    int src = edges[t * 2 * N_EDGES + e];
    int dst = edges[(t * 2 + 1) * N_EDGES + e];
    int pos = g_rowptr[t * (N_NODES + 1) + dst] + atomicAdd(&g_cur[t * N_NODES + dst], 1);
    g_col[t * N_EDGES + pos] = src;
}

// ---------------- weight pre-sum + prep ----------------
__global__ void k_wsum(const float* __restrict__ Wr, const float* __restrict__ bl) {
    int i = blockIdx.x * blockDim.x + threadIdx.x;
    if (i < 2 * C * C) {
        int l = i / (C * C), idx = i - l * (C * C);
        g_wsum[i] = Wr[(l * 3 + 0) * C * C + idx] + Wr[(l * 3 + 1) * C * C + idx]
                  + Wr[(l * 3 + 2) * C * C + idx];
    }
    if (i < 2 * C) {
        int l = i / C, cc = i - l * C;
        g_bsum[i] = bl[(l * 3 + 0) * C + cc] + bl[(l * 3 + 1) * C + cc] + bl[(l * 3 + 2) * C + cc];
    }
}
// mats: 0-2 Wp, 3-5 Wl0, 6-8 Wr0, 9-14 Wl, 15-16 wsum.  out[m][n][k] = split(W[m][k][n])
__global__ void k_wprep(const float* __restrict__ Wp, const float* __restrict__ Wl0,
                        const float* __restrict__ Wr0, const float* __restrict__ Wl) {
    int m = blockIdx.y;
    const float* src;
    if (m < 3) src = Wp + (size_t)m * C * C;
    else if (m < 6) src = Wl0 + (size_t)(m - 3) * C * C;
    else if (m < 9) src = Wr0 + (size_t)(m - 6) * C * C;
    else if (m < 15) src = Wl + (size_t)(m - 9) * C * C;
    else src = g_wsum + (size_t)(m - 15) * C * C;
    __shared__ float tile[32][33];
    int txt = (blockIdx.x & 3) * 32, tyt = (blockIdx.x >> 2) * 32;
    int tx = threadIdx.x, ty = threadIdx.y;
    #pragma unroll
    for (int i = 0; i < 4; i++)
        tile[ty + i * 8][tx] = src[(size_t)(tyt + ty + i * 8) * C + txt + tx];
    __syncthreads();
    #pragma unroll
    for (int i = 0; i < 4; i++) {
        int n = txt + ty + i * 8, k = tyt + tx;
        float v = tile[tx][ty + i * 8];
        __nv_bfloat16 hi, lo; split2(v, hi, lo);
        g_wth[(size_t)m * C * C + n * C + k] = hi;
        g_wtl[(size_t)m * C * C + n * C + k] = lo;
    }
}
// split x once into bf16 planes
__global__ void k_xprep(const float* __restrict__ x) {
    int i = blockIdx.x * blockDim.x + threadIdx.x;
    if (i * 4 >= NC) return;
    float4 v = *reinterpret_cast<const float4*>(&x[(size_t)i * 4]);
    __nv_bfloat162 hA, hB, lA, lB;
    split2(v.x, hA.x, lA.x); split2(v.y, hA.y, lA.y);
    split2(v.z, hB.x, lB.x); split2(v.w, hB.y, lB.y);
    uint2 uh, ul;
    uh.x = *reinterpret_cast<uint32_t*>(&hA); uh.y = *reinterpret_cast<uint32_t*>(&hB);
    ul.x = *reinterpret_cast<uint32_t*>(&lA); ul.y = *reinterpret_cast<uint32_t*>(&lB);
    *reinterpret_cast<uint2*>(&g_xh[(size_t)i * 4]) = uh;
    *reinterpret_cast<uint2*>(&g_xl[(size_t)i * 4]) = ul;
}

// ---------------- fused 3-type mean aggregation -> bf16 hi/lo planes ----------------
__global__ void k_agg3(const float* __restrict__ f0, const float* __restrict__ f1,
                       const float* __restrict__ f2) {
    int w = (blockIdx.x * blockDim.x + threadIdx.x) >> 5;
    int lane = threadIdx.x & 31;
    if (w >= N_NODES) return;
    const float* feats[3] = {f0, f1, f2};
    #pragma unroll
    for (int t = 0; t < 3; t++) {
        const int* rp = &g_rowptr[t * (N_NODES + 1)];
        int s = rp[w], e = rp[w + 1];
        const int* col = &g_col[t * N_EDGES];
        const float* feat = feats[t];
        float4 acc = make_float4(0.f, 0.f, 0.f, 0.f);
        for (int j = s; j < e; j++) {
            int src = col[j];
            float4 v = *reinterpret_cast<const float4*>(&feat[(size_t)src * C + lane * 4]);
            acc.x += v.x; acc.y += v.y; acc.z += v.z; acc.w += v.w;
        }
        float inv = g_invdeg[t * N_NODES + w];
        acc.x *= inv; acc.y *= inv; acc.z *= inv; acc.w *= inv;
        __nv_bfloat162 hA, hB, lA, lB;
        split2(acc.x, hA.x, lA.x); split2(acc.y, hA.y, lA.y);
        split2(acc.z, hB.x, lB.x); split2(acc.w, hB.y, lB.y);
        size_t off = (size_t)t * NC + (size_t)w * C + lane * 4;
        uint2 uh, ul;
        uh.x = *reinterpret_cast<uint32_t*>(&hA); uh.y = *reinterpret_cast<uint32_t*>(&hB);
        ul.x = *reinterpret_cast<uint32_t*>(&lA); ul.y = *reinterpret_cast<uint32_t*>(&lB);
        *reinterpret_cast<uint2*>(&g_ah[off]) = uh;
        *reinterpret_cast<uint2*>(&g_al[off]) = ul;
    }
}

// ---------------- fused relu + LayerNorm (warp per row) -> h fp32 + planes ----------------
__global__ void k_relu_ln_pl(const float* __restrict__ in,
                             const float* __restrict__ g, const float* __restrict__ b) {
    int w = (blockIdx.x * blockDim.x + threadIdx.x) >> 5;
    int lane = threadIdx.x & 31;
    if (w >= N_NODES) return;
    float4 v = *reinterpret_cast<const float4*>(&in[(size_t)w * C + lane * 4]);
    v.x = fmaxf(v.x * (1.f / 3.f), 0.f);
    v.y = fmaxf(v.y * (1.f / 3.f), 0.f);
    v.z = fmaxf(v.z * (1.f / 3.f), 0.f);
    v.w = fmaxf(v.w * (1.f / 3.f), 0.f);
    float s = v.x + v.y + v.z + v.w;
    #pragma unroll
    for (int off = 16; off > 0; off >>= 1) s += __shfl_xor_sync(0xffffffffu, s, off);
    float mean = s * (1.f / 128.f);
    float dx = v.x - mean, dy = v.y - mean, dz = v.z - mean, dw = v.w - mean;
    float ss = dx * dx + dy * dy + dz * dz + dw * dw;
    #pragma unroll
    for (int off = 16; off > 0; off >>= 1) ss += __shfl_xor_sync(0xffffffffu, ss, off);
    float rstd = rsqrtf(ss * (1.f / 128.f) + LN_EPS);
    float4 gg = *reinterpret_cast<const float4*>(&g[lane * 4]);
    float4 bb = *reinterpret_cast<const float4*>(&b[lane * 4]);
    float4 o;
    o.x = dx * rstd * gg.x + bb.x;
    o.y = dy * rstd * gg.y + bb.y;
    o.z = dz * rstd * gg.z + bb.z;
    o.w = dw * rstd * gg.w + bb.w;
    size_t off0 = (size_t)w * C + lane * 4;
    *reinterpret_cast<float4*>(&g_h[off0]) = o;
    __nv_bfloat162 hA, hB, lA, lB;
    split2(o.x, hA.x, lA.x); split2(o.y, hA.y, lA.y);
    split2(o.z, hB.x, lB.x); split2(o.w, hB.y, lB.y);
    uint2 uh, ul;
    uh.x = *reinterpret_cast<uint32_t*>(&hA); uh.y = *reinterpret_cast<uint32_t*>(&hB);
    ul.x = *reinterpret_cast<uint32_t*>(&lA); ul.y = *reinterpret_cast<uint32_t*>(&lB);
    *reinterpret_cast<uint2*>(&g_hh[off0]) = uh;
    *reinterpret_cast<uint2*>(&g_hl[off0]) = ul;
}

// ---------------- one 128x128x32 stage: ldmatrix + dependency-spread passes ----------------
__device__ __forceinline__ void mma_stage(
    uint32_t Ahi, uint32_t Alo, uint32_t Bhi, uint32_t Blo,
    int wm, int wn, int lane, float (*acc)[8][4])
{
    int aRow = lane & 15;
    uint32_t aColB = ((lane >> 4) & 1) * 16;
    int bRow = (lane & 7) | (((lane >> 4) & 1) << 3);
    uint32_t bColB = ((lane >> 3) & 1) * 16;
    uint32_t aoff0 = (uint32_t)((wm * 32 + aRow) * 80) + aColB;
    uint32_t aoff1 = aoff0 + 16 * 80;
    uint32_t boff = (uint32_t)((wn * 64 + bRow) * 80) + bColB;
    #pragma unroll
    for (int ks = 0; ks < 2; ks++) {
        uint32_t kb = ks * 32;
        uint32_t ah[2][4], al[2][4];
        ldsm4(Ahi + aoff0 + kb, ah[0][0], ah[0][1], ah[0][2], ah[0][3]);
        ldsm4(Ahi + aoff1 + kb, ah[1][0], ah[1][1], ah[1][2], ah[1][3]);
        ldsm4(Alo + aoff0 + kb, al[0][0], al[0][1], al[0][2], al[0][3]);
        ldsm4(Alo + aoff1 + kb, al[1][0], al[1][1], al[1][2], al[1][3]);
        #pragma unroll
        for (int q = 0; q < 2; q++) {
            uint32_t nq = boff + (uint32_t)(q * 32 * 80) + kb;
            uint32_t bh[4][2], bl[4][2];
            ldsm4(Bhi + nq,           bh[0][0], bh[0][1], bh[1][0], bh[1][1]);
            ldsm4(Bhi + nq + 16 * 80, bh[2][0], bh[2][1], bh[3][0], bh[3][1]);
            ldsm4(Blo + nq,           bl[0][0], bl[0][1], bl[1][0], bl[1][1]);
            ldsm4(Blo + nq + 16 * 80, bl[2][0], bl[2][1], bl[3][0], bl[3][1]);
            #pragma unroll
            for (int j = 0; j < 4; j++) {
                mma_bf16(acc[0][q * 4 + j], ah[0], bh[j][0], bh[j][1]);
                mma_bf16(acc[1][q * 4 + j], ah[1], bh[j][0], bh[j][1]);
            }
            #pragma unroll
            for (int j = 0; j < 4; j++) {
                mma_bf16(acc[0][q * 4 + j], ah[0], bl[j][0], bl[j][1]);
                mma_bf16(acc[1][q * 4 + j], ah[1], bl[j][0], bl[j][1]);
            }
            #pragma unroll
            for (int j = 0; j < 4; j++) {
                mma_bf16(acc[0][q * 4 + j], al[0], bh[j][0], bh[j][1]);
                mma_bf16(acc[1][q * 4 + j], al[1], bh[j][0], bh[j][1]);
            }
        }
    }
}

// ---------------- unified streaming GEMM (cp.async double-buffered) ----------------
// acc = sum_c A_c @ W_c ; then epilogue by mode:
//  0: out = relu(acc+bias)
//  1: out += L2rownorm(acc+bias)          (RMW)
//  2: out = (acc+bias)/3
//  3: out = LN(relu((acc+bias)/3)) + write g_hh/g_hl planes
#define SMEM_GEMM_BYTES (8 * CB)   // 81920, 2 CTAs/SM
__global__ __launch_bounds__(256, 2) void k_gemm(
    const __nv_bfloat16* __restrict__ A0h, const __nv_bfloat16* __restrict__ A0l,
    const __nv_bfloat16* __restrict__ A1h, const __nv_bfloat16* __restrict__ A1l,
    const __nv_bfloat16* __restrict__ A2h, const __nv_bfloat16* __restrict__ A2l,
    const __nv_bfloat16* __restrict__ A3h, const __nv_bfloat16* __restrict__ A3l,
    int m0, int m1, int m2, int m3, int nChunks,
    const float* __restrict__ bias, const float* __restrict__ lng,
    const float* __restrict__ lnb, float* __restrict__ outf, int mode)
{
    extern __shared__ __align__(16) char smem[];
    uint32_t sb = smem_u32(smem);
    int t = threadIdx.x, lane = t & 31, wid = t >> 5;
    int g = lane >> 2, tg = lane & 3;
    int wm = wid & 3, wn = wid >> 2;
    int row0 = blockIdx.x * 128;
    int ar = t >> 1, sel = t & 1;
    uint32_t soff = ar * 80 + sel * 32;
    int gr = row0 + ar;
    bool rvalid = gr < N_NODES;
    int grc = rvalid ? gr : (N_NODES - 1);
    int ssz = rvalid ? 16 : 0;

    const __nv_bfloat16* Ah[4] = {A0h, A1h, A2h, A3h};
    const __nv_bfloat16* Al[4] = {A0l, A1l, A2l, A3l};
    int mats[4] = {m0, m1, m2, m3};

    auto issue = [&](int s) {
        uint32_t slot = sb + (s & 1) * (4 * CB);
        int c = s >> 2, kc = (s & 3) * 32;
        size_t ae = (size_t)grc * C + kc + sel * 16;
        cp16(slot + soff, Ah[c] + ae, ssz);
        cp16(slot + soff + 16, Ah[c] + ae + 8, ssz);
        cp16(slot + CB + soff, Al[c] + ae, ssz);
        cp16(slot + CB + soff + 16, Al[c] + ae + 8, ssz);
        size_t be = (size_t)mats[c] * C * C + (size_t)ar * C + kc + sel * 16;
        cp16(slot + 2 * CB + soff, g_wth + be, 16);
        cp16(slot + 2 * CB + soff + 16, g_wth + be + 8, 16);
        cp16(slot + 3 * CB + soff, g_wtl + be, 16);
        cp16(slot + 3 * CB + soff + 16, g_wtl + be + 8, 16);
        CP_COMMIT();
    };

    float acc[2][8][4];
    #pragma unroll
    for (int mi = 0; mi < 2; mi++)
        #pragma unroll
        for (int ni = 0; ni < 8; ni++)
            #pragma unroll
            for (int r = 0; r < 4; r++) acc[mi][ni][r] = 0.f;

    int nStages = nChunks * 4;
    issue(0);
    for (int s = 0; s < nStages; s++) {
        if (s + 1 < nStages) { issue(s + 1); CP_WAIT1(); } else CP_WAIT0();
        __syncthreads();
        uint32_t slot = sb + (s & 1) * (4 * CB);
        mma_stage(slot, slot + CB, slot + 2 * CB, slot + 3 * CB, wm, wn, lane, acc);
        __syncthreads();
    }

    // ---- epilogues ----
    if (mode == 0) {
        #pragma unroll
        for (int mi = 0; mi < 2; mi++) {
            int r0 = row0 + wm * 32 + mi * 16 + g, r1 = r0 + 8;
            #pragma unroll
            for (int ni = 0; ni < 8; ni++) {
                int coln = wn * 64 + ni * 8 + tg * 2;
                float2 bv = *reinterpret_cast<const float2*>(&bias[coln]);
                float2 o0, o1;
                o0.x = fmaxf(acc[mi][ni][0] + bv.x, 0.f);
                o0.y = fmaxf(acc[mi][ni][1] + bv.y, 0.f);
                o1.x = fmaxf(acc[mi][ni][2] + bv.x, 0.f);
                o1.y = fmaxf(acc[mi][ni][3] + bv.y, 0.f);
                if (r0 < N_NODES) *reinterpret_cast<float2*>(&outf[(size_t)r0 * C + coln]) = o0;
                if (r1 < N_NODES) *reinterpret_cast<float2*>(&outf[(size_t)r1 * C + coln]) = o1;
            }
        }
        return;
    }

    if (mode == 1) {
        // bias, per-row L2 norm, accumulate into outf
        #pragma unroll
        for (int ni = 0; ni < 8; ni++) {
            int coln = wn * 64 + ni * 8 + tg * 2;
            float2 bv = *reinterpret_cast<const float2*>(&bias[coln]);
            #pragma unroll
            for (int mi = 0; mi < 2; mi++) {
                acc[mi][ni][0] += bv.x; acc[mi][ni][1] += bv.y;
                acc[mi][ni][2] += bv.x; acc[mi][ni][3] += bv.y;
            }
        }
        float* red = (float*)smem;       // [128][2]
        float* invn = red + 256;         // [128]
        float ss0[2] = {0.f, 0.f}, ss1[2] = {0.f, 0.f};
        #pragma unroll
        for (int mi = 0; mi < 2; mi++)
            #pragma unroll
            for (int ni = 0; ni < 8; ni++) {
                ss0[mi] += acc[mi][ni][0] * acc[mi][ni][0] + acc[mi][ni][1] * acc[mi][ni][1];
                ss1[mi] += acc[mi][ni][2] * acc[mi][ni][2] + acc[mi][ni][3] * acc[mi][ni][3];
            }
        #pragma unroll
        for (int mi = 0; mi < 2; mi++) {
            ss0[mi] += __shfl_xor_sync(0xffffffffu, ss0[mi], 1);
            ss0[mi] += __shfl_xor_sync(0xffffffffu, ss0[mi], 2);
            ss1[mi] += __shfl_xor_sync(0xffffffffu, ss1[mi], 1);
            ss1[mi] += __shfl_xor_sync(0xffffffffu, ss1[mi], 2);
        }
        if (tg == 0) {
            #pragma unroll
            for (int mi = 0; mi < 2; mi++) {
                red[(wm * 32 + mi * 16 + g) * 2 + wn] = ss0[mi];
                red[(wm * 32 + mi * 16 + 8 + g) * 2 + wn] = ss1[mi];
            }
        }
        __syncthreads();
        if (t < 128) invn[t] = 1.f / fmaxf(sqrtf(red[t * 2] + red[t * 2 + 1]), L2_EPS);
        __syncthreads();
        #pragma unroll
        for (int mi = 0; mi < 2; mi++) {
            int lr0 = wm * 32 + mi * 16 + g;
            int r0 = row0 + lr0, r1 = r0 + 8;
            float i0 = invn[lr0], i1 = invn[lr0 + 8];
            #pragma unroll
            for (int ni = 0; ni < 8; ni++) {
                int coln = wn * 64 + ni * 8 + tg * 2;
                if (r0 < N_NODES) {
                    float2 o = *reinterpret_cast<float2*>(&outf[(size_t)r0 * C + coln]);
                    o.x += acc[mi][ni][0] * i0;
                    o.y += acc[mi][ni][1] * i0;
                    *reinterpret_cast<float2*>(&outf[(size_t)r0 * C + coln]) = o;
                }
                if (r1 < N_NODES) {
                    float2 o = *reinterpret_cast<float2*>(&outf[(size_t)r1 * C + coln]);
                    o.x += acc[mi][ni][2] * i1;
                    o.y += acc[mi][ni][3] * i1;
                    *reinterpret_cast<float2*>(&outf[(size_t)r1 * C + coln]) = o;
                }
            }
        }
        return;
    }

    // modes 2/3: bias + /3 (+relu for 3)
    const float sc = 1.f / 3.f;
    #pragma unroll
    for (int ni = 0; ni < 8; ni++) {
        int coln = wn * 64 + ni * 8 + tg * 2;
        float2 bv = *reinterpret_cast<const float2*>(&bias[coln]);
        #pragma unroll
        for (int mi = 0; mi < 2; mi++) {
            acc[mi][ni][0] = (acc[mi][ni][0] + bv.x) * sc;
            acc[mi][ni][1] = (acc[mi][ni][1] + bv.y) * sc;
            acc[mi][ni][2] = (acc[mi][ni][2] + bv.x) * sc;
            acc[mi][ni][3] = (acc[mi][ni][3] + bv.y) * sc;
            if (mode == 3) {
                acc[mi][ni][0] = fmaxf(acc[mi][ni][0], 0.f);
                acc[mi][ni][1] = fmaxf(acc[mi][ni][1], 0.f);
                acc[mi][ni][2] = fmaxf(acc[mi][ni][2], 0.f);
                acc[mi][ni][3] = fmaxf(acc[mi][ni][3], 0.f);
            }
        }
    }

    if (mode == 2) {
        #pragma unroll
        for (int mi = 0; mi < 2; mi++) {
            int r0 = row0 + wm * 32 + mi * 16 + g, r1 = r0 + 8;
            #pragma unroll
            for (int ni = 0; ni < 8; ni++) {
                int coln = wn * 64 + ni * 8 + tg * 2;
                if (r0 < N_NODES) {
                    float2 o; o.x = acc[mi][ni][0]; o.y = acc[mi][ni][1];
                    *reinterpret_cast<float2*>(&outf[(size_t)r0 * C + coln]) = o;
                }
                if (r1 < N_NODES) {
                    float2 o; o.x = acc[mi][ni][2]; o.y = acc[mi][ni][3];
                    *reinterpret_cast<float2*>(&outf[(size_t)r1 * C + coln]) = o;
                }
            }
        }
        return;
    }

    // mode 3: fused LayerNorm + h planes
    {
        float* red_s = (float*)smem;     // [128][2]
        float* red_q = red_s + 256;      // [128][2]
        float* rmean = red_q + 256;      // [128]
        float* rstdv = rmean + 128;      // [128]
        float s0[2] = {0.f, 0.f}, q0[2] = {0.f, 0.f};
        float s1[2] = {0.f, 0.f}, q1[2] = {0.f, 0.f};
        #pragma unroll
        for (int mi = 0; mi < 2; mi++)
            #pragma unroll
            for (int ni = 0; ni < 8; ni++) {
                s0[mi] += acc[mi][ni][0] + acc[mi][ni][1];
                q0[mi] += acc[mi][ni][0] * acc[mi][ni][0] + acc[mi][ni][1] * acc[mi][ni][1];
                s1[mi] += acc[mi][ni][2] + acc[mi][ni][3];
                q1[mi] += acc[mi][ni][2] * acc[mi][ni][2] + acc[mi][ni][3] * acc[mi][ni][3];
            }
        #pragma unroll
        for (int mi = 0; mi < 2; mi++) {
            s0[mi] += __shfl_xor_sync(0xffffffffu, s0[mi], 1);
            s0[mi] += __shfl_xor_sync(0xffffffffu, s0[mi], 2);
            q0[mi] += __shfl_xor_sync(0xffffffffu, q0[mi], 1);
            q0[mi] += __shfl_xor_sync(0xffffffffu, q0[mi], 2);
            s1[mi] += __shfl_xor_sync(0xffffffffu, s1[mi], 1);
            s1[mi] += __shfl_xor_sync(0xffffffffu, s1[mi], 2);
            q1[mi] += __shfl_xor_sync(0xffffffffu, q1[mi], 1);
            q1[mi] += __shfl_xor_sync(0xffffffffu, q1[mi], 2);
        }
        if (tg == 0) {
            #pragma unroll
            for (int mi = 0; mi < 2; mi++) {
                int lr = wm * 32 + mi * 16 + g;
                red_s[lr * 2 + wn] = s0[mi];
                red_q[lr * 2 + wn] = q0[mi];
                red_s[(lr + 8) * 2 + wn] = s1[mi];
                red_q[(lr + 8) * 2 + wn] = q1[mi];
            }
        }
        __syncthreads();
        if (t < 128) {
            float ssum = red_s[t * 2] + red_s[t * 2 + 1];
            float qsum = red_q[t * 2] + red_q[t * 2 + 1];
            float mean = ssum * (1.f / 128.f);
            float var = qsum * (1.f / 128.f) - mean * mean;
            rmean[t] = mean;
            rstdv[t] = rsqrtf(fmaxf(var, 0.f) + LN_EPS);
        }
        __syncthreads();
        #pragma unroll
        for (int mi = 0; mi < 2; mi++) {
            int lr0 = wm * 32 + mi * 16 + g;
            int r0 = row0 + lr0, r1 = r0 + 8;
            float m0v = rmean[lr0], d0 = rstdv[lr0];
            float m1v = rmean[lr0 + 8], d1 = rstdv[lr0 + 8];
            #pragma unroll
            for (int ni = 0; ni < 8; ni++) {
                int coln = wn * 64 + ni * 8 + tg * 2;
                float2 gv = *reinterpret_cast<const float2*>(&lng[coln]);
                float2 bb = *reinterpret_cast<const float2*>(&lnb[coln]);
                if (r0 < N_NODES) {
                    float2 o;
                    o.x = (acc[mi][ni][0] - m0v) * d0 * gv.x + bb.x;
                    o.y = (acc[mi][ni][1] - m0v) * d0 * gv.y + bb.y;
                    *reinterpret_cast<float2*>(&outf[(size_t)r0 * C + coln]) = o;
                    __nv_bfloat162 hh, ll;
                    split2(o.x, hh.x, ll.x); split2(o.y, hh.y, ll.y);
                    *reinterpret_cast<__nv_bfloat162*>(&g_hh[(size_t)r0 * C + coln]) = hh;
                    *reinterpret_cast<__nv_bfloat162*>(&g_hl[(size_t)r0 * C + coln]) = ll;
                }
                if (r1 < N_NODES) {
                    float2 o;
                    o.x = (acc[mi][ni][2] - m1v) * d1 * gv.x + bb.x;
                    o.y = (acc[mi][ni][3] - m1v) * d1 * gv.y + bb.y;
                    *reinterpret_cast<float2*>(&outf[(size_t)r1 * C + coln]) = o;
                    __nv_bfloat162 hh, ll;
                    split2(o.x, hh.x, ll.x); split2(o.y, hh.y, ll.y);
                    *reinterpret_cast<__nv_bfloat162*>(&g_hh[(size_t)r1 * C + coln]) = hh;
                    *reinterpret_cast<__nv_bfloat162*>(&g_hl[(size_t)r1 * C + coln]) = ll;
                }
            }
        }
    }
}

// ---------------- host orchestration ----------------
extern "C" void kernel_launch(void* const* d_in, const int* in_sizes, int n_in,
                              void* d_out, int out_size) {
    const float* x    = (const float*)d_in[0];
    const int*   edges = (const int*)d_in[1];
    const float* Wp   = (const float*)d_in[2];
    const float* bp   = (const float*)d_in[3];
    const float* Wl0  = (const float*)d_in[4];
    const float* bl0  = (const float*)d_in[5];
    const float* Wr0  = (const float*)d_in[6];
    const float* Wl   = (const float*)d_in[7];
    const float* bl   = (const float*)d_in[8];
    const float* Wr   = (const float*)d_in[9];
    const float* ln_g = (const float*)d_in[10];
    const float* ln_b = (const float*)d_in[11];
    float* out = (float*)d_out;

    void* p;
    float *msg0, *msg1, *msg2, *accb, *h, *bsum;
    __nv_bfloat16 *xh, *xl, *ah, *al, *hh, *hl;
    cudaGetSymbolAddress(&p, g_msg0); msg0 = (float*)p;
    cudaGetSymbolAddress(&p, g_msg1); msg1 = (float*)p;
    cudaGetSymbolAddress(&p, g_msg2); msg2 = (float*)p;
    cudaGetSymbolAddress(&p, g_accb); accb = (float*)p;
    cudaGetSymbolAddress(&p, g_h);    h = (float*)p;
    cudaGetSymbolAddress(&p, g_bsum); bsum = (float*)p;
    cudaGetSymbolAddress(&p, g_xh);   xh = (__nv_bfloat16*)p;
    cudaGetSymbolAddress(&p, g_xl);   xl = (__nv_bfloat16*)p;
    cudaGetSymbolAddress(&p, g_ah);   ah = (__nv_bfloat16*)p;
    cudaGetSymbolAddress(&p, g_al);   al = (__nv_bfloat16*)p;
    cudaGetSymbolAddress(&p, g_hh);   hh = (__nv_bfloat16*)p;
    cudaGetSymbolAddress(&p, g_hl);   hl = (__nv_bfloat16*)p;

    cudaFuncSetAttribute(k_gemm, cudaFuncAttributeMaxDynamicSharedMemorySize, SMEM_GEMM_BYTES);

    int nbScan = (N_NODES + 1023) / 1024;
    dim3 gScan(nbScan, ET);
    int gMma = (N_NODES + 127) / 128;
    int gWarp = (N_NODES * 32 + 255) / 256;

    // launches 1-3: weight + x prep
    k_wsum<<<(2 * C * C + 255) / 256, 256>>>(Wr, bl);
    k_wprep<<<dim3(16, 17), dim3(32, 8)>>>(Wp, Wl0, Wr0, Wl);
    k_xprep<<<(NC / 4 + 255) / 256, 256>>>(x);

    // launch 4 (ncu capture slot): projection GEMM, type 0
    k_gemm<<<gMma, 256, SMEM_GEMM_BYTES>>>(xh, xl, xh, xl, xh, xl, xh, xl,
                                           0, 0, 0, 0, 1, bp, ln_g, ln_b, msg0, 0);
    k_gemm<<<gMma, 256, SMEM_GEMM_BYTES>>>(xh, xl, xh, xl, xh, xl, xh, xl,
                                           1, 0, 0, 0, 1, bp + C, ln_g, ln_b, msg1, 0);
    k_gemm<<<gMma, 256, SMEM_GEMM_BYTES>>>(xh, xl, xh, xl, xh, xl, xh, xl,
                                           2, 0, 0, 0, 1, bp + 2 * C, ln_g, ln_b, msg2, 0);

    // CSR build + zero
    k_zero_int<<<(ET * N_NODES + 255) / 256, 256>>>();
    k_hist<<<(ET * N_EDGES + 255) / 256, 256>>>(edges);
    k_scan1<<<gScan, 1024>>>();
    k_scan2<<<1, 32>>>();
    k_scan3<<<gScan, 1024>>>();
    k_invdeg<<<(ET * N_NODES + 255) / 256, 256>>>();
    k_scatter<<<(ET * N_EDGES + 255) / 256, 256>>>(edges);
    k_zero_acc<<<(NC + 255) / 256, 256>>>();

    // layer 0: aggregate msgs -> agg planes; 3x dual GEMM (norm-accumulate); relu/3+LN -> h
    k_agg3<<<gWarp, 256>>>(msg0, msg1, msg2);
    for (int t = 0; t < 3; t++)
        k_gemm<<<gMma, 256, SMEM_GEMM_BYTES>>>(
            ah + (size_t)t * NC, al + (size_t)t * NC, xh, xl, xh, xl, xh, xl,
            3 + t, 6 + t, 0, 0, 2, bl0 + t * C, ln_g, ln_b, accb, 1);
    k_relu_ln_pl<<<gWarp, 256>>>(accb, ln_g, ln_b);

    // layer 1: h = LN(relu((Σ agg@Wl + h@ΣWr + Σb)/3)) + planes
    k_agg3<<<gWarp, 256>>>(h, h, h);
    k_gemm<<<gMma, 256, SMEM_GEMM_BYTES>>>(
        ah, al, ah + (size_t)NC, al + (size_t)NC, ah + 2 * (size_t)NC, al + 2 * (size_t)NC,
        hh, hl, 9, 10, 11, 15, 4, bsum, ln_g + C, ln_b + C, h, 3);

    // layer 2: out = (Σ agg@Wl + h@ΣWr + Σb)/3
    k_agg3<<<gWarp, 256>>>(h, h, h);
    k_gemm<<<gMma, 256, SMEM_GEMM_BYTES>>>(
        ah, al, ah + (size_t)NC, al + (size_t)NC, ah + 2 * (size_t)NC, al + 2 * (size_t)NC,
        hh, hl, 12, 13, 14, 16, 4, bsum + C, ln_g, ln_b, out, 2);
}

// round 11
// speedup vs baseline: 1.0099x; 1.0099x over previous
#include <cuda_runtime.h>
#include <cuda_bf16.h>
#include <cstdint>

#define N_NODES 100000
#define N_EDGES 500000
#define ET 3
#define C 128
#define NC (N_NODES * C)
#define LN_EPS 1e-5f
#define L2_EPS 1e-12f

// BK=16 stage geometry: plane = 128 rows x 24 halves (16 data + 8 pad)
#define P2 24
#define CH2 (128 * P2)             // halves per plane (3072)
#define CB2 (CH2 * 2)              // bytes per plane (6144)
#define STAGE_B (4 * CB2)          // bytes per stage (24576)
#define NSTAGE 4
#define SMEM_GEMM_BYTES (NSTAGE * STAGE_B)   // 98304; 2 CTAs/SM (192KB)

// ---------------- scratch (static device globals; no allocation) ----------------
__device__ float g_msg0[NC];
__device__ float g_msg1[NC];
__device__ float g_msg2[NC];
__device__ float g_accb[NC];
__device__ float g_h[NC];
__device__ __align__(16) __nv_bfloat16 g_xh[NC];
__device__ __align__(16) __nv_bfloat16 g_xl[NC];
__device__ __align__(16) __nv_bfloat16 g_ah[3 * NC];   // agg planes hi
__device__ __align__(16) __nv_bfloat16 g_al[3 * NC];   // agg planes lo
__device__ __align__(16) __nv_bfloat16 g_hh[NC];       // h planes
__device__ __align__(16) __nv_bfloat16 g_hl[NC];
__device__ __align__(16) __nv_bfloat16 g_wth[17 * C * C];  // transposed+split weights [n][k]
__device__ __align__(16) __nv_bfloat16 g_wtl[17 * C * C];
__device__ float g_wsum[2 * C * C];
__device__ float g_bsum[2 * C];
__device__ float g_invdeg[ET * N_NODES];
__device__ int g_cnt[ET * N_NODES];
__device__ int g_cur[ET * N_NODES];
__device__ int g_rowptr[ET * (N_NODES + 1)];
__device__ int g_col[ET * N_EDGES];
__device__ int g_bofs[ET * 128];

// ---------------- helpers ----------------
__device__ __forceinline__ uint32_t smem_u32(const void* p) {
    uint32_t a;
    asm("{ .reg .u64 t; cvta.to.shared.u64 t, %1; cvt.u32.u64 %0, t; }" : "=r"(a) : "l"(p));
    return a;
}
__device__ __forceinline__ void cp16(uint32_t dst, const void* src, int srcsize) {
    asm volatile("cp.async.cg.shared.global [%0], [%1], 16, %2;"
                 :: "r"(dst), "l"(src), "r"(srcsize));
}
#define CP_COMMIT() asm volatile("cp.async.commit_group;" ::: "memory")
#define CP_WAIT2()  asm volatile("cp.async.wait_group 2;" ::: "memory")

__device__ __forceinline__ void split2(float x, __nv_bfloat16& hi, __nv_bfloat16& lo) {
    hi = __float2bfloat16_rn(x);
    lo = __float2bfloat16_rn(x - __bfloat162float(hi));
}
__device__ __forceinline__ void mma_bf16(float* d, const uint32_t* a, uint32_t b0, uint32_t b1) {
    asm volatile(
        "mma.sync.aligned.m16n8k16.row.col.f32.bf16.bf16.f32 "
        "{%0,%1,%2,%3}, {%4,%5,%6,%7}, {%8,%9}, {%0,%1,%2,%3};"
        : "+f"(d[0]), "+f"(d[1]), "+f"(d[2]), "+f"(d[3])
        : "r"(a[0]), "r"(a[1]), "r"(a[2]), "r"(a[3]), "r"(b0), "r"(b1));
}
__device__ __forceinline__ void ldsm4(uint32_t a, uint32_t& r0, uint32_t& r1,
                                      uint32_t& r2, uint32_t& r3) {
    asm volatile("ldmatrix.sync.aligned.m8n8.x4.shared.b16 {%0,%1,%2,%3}, [%4];"
                 : "=r"(r0), "=r"(r1), "=r"(r2), "=r"(r3) : "r"(a));
}

// ---------------- CSR build ----------------
__global__ void k_zero_int() {
    int i = blockIdx.x * blockDim.x + threadIdx.x;
    if (i < ET * N_NODES) { g_cnt[i] = 0; g_cur[i] = 0; }
}
__global__ void k_zero_acc() {
    int i = blockIdx.x * blockDim.x + threadIdx.x;
    if (i < NC) g_accb[i] = 0.f;
}
__global__ void k_hist(const int* __restrict__ edges) {
    int i = blockIdx.x * blockDim.x + threadIdx.x;
    if (i >= ET * N_EDGES) return;
    int t = i / N_EDGES, e = i - t * N_EDGES;
    int dst = edges[(t * 2 + 1) * N_EDGES + e];
    atomicAdd(&g_cnt[t * N_NODES + dst], 1);
}
__global__ void k_scan1() {
    int t = blockIdx.y;
    int i = blockIdx.x * 1024 + threadIdx.x;
    __shared__ int sm[1024];
    int v = (i < N_NODES) ? g_cnt[t * N_NODES + i] : 0;
    sm[threadIdx.x] = v;
    __syncthreads();
    for (int off = 1; off < 1024; off <<= 1) {
        int add = (threadIdx.x >= off) ? sm[threadIdx.x - off] : 0;
        __syncthreads();
        sm[threadIdx.x] += add;
        __syncthreads();
    }
    if (i < N_NODES) g_rowptr[t * (N_NODES + 1) + i] = sm[threadIdx.x] - v;
    if (threadIdx.x == 1023) g_bofs[t * 128 + blockIdx.x] = sm[1023];
}
__global__ void k_scan2() {
    int t = threadIdx.x;
    if (t >= ET) return;
    int nb = (N_NODES + 1023) / 1024;
    int run = 0;
    for (int b = 0; b < nb; b++) { int v = g_bofs[t * 128 + b]; g_bofs[t * 128 + b] = run; run += v; }
    g_rowptr[t * (N_NODES + 1) + N_NODES] = run;
}
__global__ void k_scan3() {
    int t = blockIdx.y;
    int i = blockIdx.x * 1024 + threadIdx.x;
    if (i < N_NODES) g_rowptr[t * (N_NODES + 1) + i] += g_bofs[t * 128 + blockIdx.x];
}
__global__ void k_invdeg() {
    int i = blockIdx.x * blockDim.x + threadIdx.x;
    if (i < ET * N_NODES) {
        int c = g_cnt[i];
        g_invdeg[i] = 1.0f / (float)(c > 1 ? c : 1);
    }
}
__global__ void k_scatter(const int* __restrict__ edges) {
    int i = blockIdx.x * blockDim.x + threadIdx.x;
    if (i >= ET * N_EDGES) return;
    int t = i / N_EDGES, e = i - t * N_EDGES;
    int src = edges[t * 2 * N_EDGES + e];
    int dst = edges[(t * 2 + 1) * N_EDGES + e];
    int pos = g_rowptr[t * (N_NODES + 1) + dst] + atomicAdd(&g_cur[t * N_NODES + dst], 1);
    g_col[t * N_EDGES + pos] = src;
}

// ---------------- weight pre-sum + prep ----------------
__global__ void k_wsum(const float* __restrict__ Wr, const float* __restrict__ bl) {
    int i = blockIdx.x * blockDim.x + threadIdx.x;
    if (i < 2 * C * C) {
        int l = i / (C * C), idx = i - l * (C * C);
        g_wsum[i] = Wr[(l * 3 + 0) * C * C + idx] + Wr[(l * 3 + 1) * C * C + idx]
                  + Wr[(l * 3 + 2) * C * C + idx];
    }
    if (i < 2 * C) {
        int l = i / C, cc = i - l * C;
        g_bsum[i] = bl[(l * 3 + 0) * C + cc] + bl[(l * 3 + 1) * C + cc] + bl[(l * 3 + 2) * C + cc];
    }
}
// mats: 0-2 Wp, 3-5 Wl0, 6-8 Wr0, 9-14 Wl, 15-16 wsum.  out[m][n][k] = split(W[m][k][n])
__global__ void k_wprep(const float* __restrict__ Wp, const float* __restrict__ Wl0,
                        const float* __restrict__ Wr0, const float* __restrict__ Wl) {
    int m = blockIdx.y;
    const float* src;
    if (m < 3) src = Wp + (size_t)m * C * C;
    else if (m < 6) src = Wl0 + (size_t)(m - 3) * C * C;
    else if (m < 9) src = Wr0 + (size_t)(m - 6) * C * C;
    else if (m < 15) src = Wl + (size_t)(m - 9) * C * C;
    else src = g_wsum + (size_t)(m - 15) * C * C;
    __shared__ float tile[32][33];
    int txt = (blockIdx.x & 3) * 32, tyt = (blockIdx.x >> 2) * 32;
    int tx = threadIdx.x, ty = threadIdx.y;
    #pragma unroll
    for (int i = 0; i < 4; i++)
        tile[ty + i * 8][tx] = src[(size_t)(tyt + ty + i * 8) * C + txt + tx];
    __syncthreads();
    #pragma unroll
    for (int i = 0; i < 4; i++) {
        int n = txt + ty + i * 8, k = tyt + tx;
        float v = tile[tx][ty + i * 8];
        __nv_bfloat16 hi, lo; split2(v, hi, lo);
        g_wth[(size_t)m * C * C + n * C + k] = hi;
        g_wtl[(size_t)m * C * C + n * C + k] = lo;
    }
}
// split x once into bf16 planes
__global__ void k_xprep(const float* __restrict__ x) {
    int i = blockIdx.x * blockDim.x + threadIdx.x;
    if (i * 4 >= NC) return;
    float4 v = *reinterpret_cast<const float4*>(&x[(size_t)i * 4]);
    __nv_bfloat162 hA, hB, lA, lB;
    split2(v.x, hA.x, lA.x); split2(v.y, hA.y, lA.y);
    split2(v.z, hB.x, lB.x); split2(v.w, hB.y, lB.y);
    uint2 uh, ul;
    uh.x = *reinterpret_cast<uint32_t*>(&hA); uh.y = *reinterpret_cast<uint32_t*>(&hB);
    ul.x = *reinterpret_cast<uint32_t*>(&lA); ul.y = *reinterpret_cast<uint32_t*>(&lB);
    *reinterpret_cast<uint2*>(&g_xh[(size_t)i * 4]) = uh;
    *reinterpret_cast<uint2*>(&g_xl[(size_t)i * 4]) = ul;
}

// ---------------- fused 3-type mean aggregation -> bf16 hi/lo planes ----------------
__global__ void k_agg3(const float* __restrict__ f0, const float* __restrict__ f1,
                       const float* __restrict__ f2) {
    int w = (blockIdx.x * blockDim.x + threadIdx.x) >> 5;
    int lane = threadIdx.x & 31;
    if (w >= N_NODES) return;
    const float* feats[3] = {f0, f1, f2};
    #pragma unroll
    for (int t = 0; t < 3; t++) {
        const int* rp = &g_rowptr[t * (N_NODES + 1)];
        int s = rp[w], e = rp[w + 1];
        const int* col = &g_col[t * N_EDGES];
        const float* feat = feats[t];
        float4 acc = make_float4(0.f, 0.f, 0.f, 0.f);
        int j = s;
        for (; j + 1 < e; j += 2) {
            int s0 = col[j], s1 = col[j + 1];
            float4 v0 = *reinterpret_cast<const float4*>(&feat[(size_t)s0 * C + lane * 4]);
            float4 v1 = *reinterpret_cast<const float4*>(&feat[(size_t)s1 * C + lane * 4]);
            acc.x += v0.x; acc.y += v0.y; acc.z += v0.z; acc.w += v0.w;
            acc.x += v1.x; acc.y += v1.y; acc.z += v1.z; acc.w += v1.w;
        }
        if (j < e) {
            int s0 = col[j];
            float4 v0 = *reinterpret_cast<const float4*>(&feat[(size_t)s0 * C + lane * 4]);
            acc.x += v0.x; acc.y += v0.y; acc.z += v0.z; acc.w += v0.w;
        }
        float inv = g_invdeg[t * N_NODES + w];
        acc.x *= inv; acc.y *= inv; acc.z *= inv; acc.w *= inv;
        __nv_bfloat162 hA, hB, lA, lB;
        split2(acc.x, hA.x, lA.x); split2(acc.y, hA.y, lA.y);
        split2(acc.z, hB.x, lB.x); split2(acc.w, hB.y, lB.y);
        size_t off = (size_t)t * NC + (size_t)w * C + lane * 4;
        uint2 uh, ul;
        uh.x = *reinterpret_cast<uint32_t*>(&hA); uh.y = *reinterpret_cast<uint32_t*>(&hB);
        ul.x = *reinterpret_cast<uint32_t*>(&lA); ul.y = *reinterpret_cast<uint32_t*>(&lB);
        *reinterpret_cast<uint2*>(&g_ah[off]) = uh;
        *reinterpret_cast<uint2*>(&g_al[off]) = ul;
    }
}

// ---------------- fused relu + LayerNorm (warp per row) -> h fp32 + planes ----------------
__global__ void k_relu_ln_pl(const float* __restrict__ in,
                             const float* __restrict__ g, const float* __restrict__ b) {
    int w = (blockIdx.x * blockDim.x + threadIdx.x) >> 5;
    int lane = threadIdx.x & 31;
    if (w >= N_NODES) return;
    float4 v = *reinterpret_cast<const float4*>(&in[(size_t)w * C + lane * 4]);
    v.x = fmaxf(v.x * (1.f / 3.f), 0.f);
    v.y = fmaxf(v.y * (1.f / 3.f), 0.f);
    v.z = fmaxf(v.z * (1.f / 3.f), 0.f);
    v.w = fmaxf(v.w * (1.f / 3.f), 0.f);
    float s = v.x + v.y + v.z + v.w;
    #pragma unroll
    for (int off = 16; off > 0; off >>= 1) s += __shfl_xor_sync(0xffffffffu, s, off);
    float mean = s * (1.f / 128.f);
    float dx = v.x - mean, dy = v.y - mean, dz = v.z - mean, dw = v.w - mean;
    float ss = dx * dx + dy * dy + dz * dz + dw * dw;
    #pragma unroll
    for (int off = 16; off > 0; off >>= 1) ss += __shfl_xor_sync(0xffffffffu, ss, off);
    float rstd = rsqrtf(ss * (1.f / 128.f) + LN_EPS);
    float4 gg = *reinterpret_cast<const float4*>(&g[lane * 4]);
    float4 bb = *reinterpret_cast<const float4*>(&b[lane * 4]);
    float4 o;
    o.x = dx * rstd * gg.x + bb.x;
    o.y = dy * rstd * gg.y + bb.y;
    o.z = dz * rstd * gg.z + bb.z;
    o.w = dw * rstd * gg.w + bb.w;
    size_t off0 = (size_t)w * C + lane * 4;
    *reinterpret_cast<float4*>(&g_h[off0]) = o;
    __nv_bfloat162 hA, hB, lA, lB;
    split2(o.x, hA.x, lA.x); split2(o.y, hA.y, lA.y);
    split2(o.z, hB.x, lB.x); split2(o.w, hB.y, lB.y);
    uint2 uh, ul;
    uh.x = *reinterpret_cast<uint32_t*>(&hA); uh.y = *reinterpret_cast<uint32_t*>(&hB);
    ul.x = *reinterpret_cast<uint32_t*>(&lA); ul.y = *reinterpret_cast<uint32_t*>(&lB);
    *reinterpret_cast<uint2*>(&g_hh[off0]) = uh;
    *reinterpret_cast<uint2*>(&g_hl[off0]) = ul;
}

// ---------------- one 128x128x16 stage: ldmatrix + dependency-spread passes ----------------
__device__ __forceinline__ void mma_stage16(
    uint32_t Ahi, uint32_t Alo, uint32_t Bhi, uint32_t Blo,
    int wm, int wn, int lane, float (*acc)[8][4])
{
    int aRow = lane & 15;
    uint32_t aColB = ((lane >> 4) & 1) * 16;
    int bRow = (lane & 7) | (((lane >> 4) & 1) << 3);
    uint32_t bColB = ((lane >> 3) & 1) * 16;
    uint32_t aoff0 = (uint32_t)((wm * 32 + aRow) * 48) + aColB;
    uint32_t aoff1 = aoff0 + 16 * 48;
    uint32_t boff = (uint32_t)((wn * 64 + bRow) * 48) + bColB;
    uint32_t ah[2][4], al[2][4];
    ldsm4(Ahi + aoff0, ah[0][0], ah[0][1], ah[0][2], ah[0][3]);
    ldsm4(Ahi + aoff1, ah[1][0], ah[1][1], ah[1][2], ah[1][3]);
    ldsm4(Alo + aoff0, al[0][0], al[0][1], al[0][2], al[0][3]);
    ldsm4(Alo + aoff1, al[1][0], al[1][1], al[1][2], al[1][3]);
    #pragma unroll
    for (int q = 0; q < 2; q++) {
        uint32_t nq = boff + (uint32_t)(q * 32 * 48);
        uint32_t bh[4][2], bl[4][2];
        ldsm4(Bhi + nq,           bh[0][0], bh[0][1], bh[1][0], bh[1][1]);
        ldsm4(Bhi + nq + 16 * 48, bh[2][0], bh[2][1], bh[3][0], bh[3][1]);
        ldsm4(Blo + nq,           bl[0][0], bl[0][1], bl[1][0], bl[1][1]);
        ldsm4(Blo + nq + 16 * 48, bl[2][0], bl[2][1], bl[3][0], bl[3][1]);
        #pragma unroll
        for (int j = 0; j < 4; j++) {
            mma_bf16(acc[0][q * 4 + j], ah[0], bh[j][0], bh[j][1]);
            mma_bf16(acc[1][q * 4 + j], ah[1], bh[j][0], bh[j][1]);
        }
        #pragma unroll
        for (int j = 0; j < 4; j++) {
            mma_bf16(acc[0][q * 4 + j], ah[0], bl[j][0], bl[j][1]);
            mma_bf16(acc[1][q * 4 + j], ah[1], bl[j][0], bl[j][1]);
        }
        #pragma unroll
        for (int j = 0; j < 4; j++) {
            mma_bf16(acc[0][q * 4 + j], al[0], bh[j][0], bh[j][1]);
            mma_bf16(acc[1][q * 4 + j], al[1], bh[j][0], bh[j][1]);
        }
    }
}

// ---------------- unified streaming GEMM (cp.async 4-deep ring, 1 sync/stage) ----------------
// acc = sum_c A_c @ W_c ; epilogue by mode:
//  0: out = relu(acc+bias)
//  1: out += L2rownorm(acc+bias)          (RMW)
//  2: out = (acc+bias)/3
//  3: out = LN(relu((acc+bias)/3)) + write g_hh/g_hl planes
__global__ __launch_bounds__(256, 2) void k_gemm(
    const __nv_bfloat16* __restrict__ A0h, const __nv_bfloat16* __restrict__ A0l,
    const __nv_bfloat16* __restrict__ A1h, const __nv_bfloat16* __restrict__ A1l,
    const __nv_bfloat16* __restrict__ A2h, const __nv_bfloat16* __restrict__ A2l,
    const __nv_bfloat16* __restrict__ A3h, const __nv_bfloat16* __restrict__ A3l,
    int m0, int m1, int m2, int m3, int nChunks,
    const float* __restrict__ bias, const float* __restrict__ lng,
    const float* __restrict__ lnb, float* __restrict__ outf, int mode)
{
    extern __shared__ __align__(16) char smem[];
    uint32_t sb = smem_u32(smem);
    int t = threadIdx.x, lane = t & 31, wid = t >> 5;
    int g = lane >> 2, tg = lane & 3;
    int wm = wid & 3, wn = wid >> 2;
    int row0 = blockIdx.x * 128;
    int ar = t >> 1, sel = t & 1;
    uint32_t soff = (uint32_t)(ar * 48 + sel * 16);
    int gr = row0 + ar;
    bool rvalid = gr < N_NODES;
    int grc = rvalid ? gr : (N_NODES - 1);
    int ssz = rvalid ? 16 : 0;

    const __nv_bfloat16* Ah[4] = {A0h, A1h, A2h, A3h};
    const __nv_bfloat16* Al[4] = {A0l, A1l, A2l, A3l};
    int mats[4] = {m0, m1, m2, m3};
    int nStages = nChunks * 8;     // K chunks of 16

    auto issue = [&](int s) {
        if (s < nStages) {
            uint32_t slot = sb + (uint32_t)(s & (NSTAGE - 1)) * STAGE_B;
            int c = s >> 3, kc = (s & 7) * 16;
            size_t ae = (size_t)grc * C + kc + sel * 8;
            cp16(slot + soff, Ah[c] + ae, ssz);
            cp16(slot + CB2 + soff, Al[c] + ae, ssz);
            size_t be = (size_t)mats[c] * C * C + (size_t)ar * C + kc + sel * 8;
            cp16(slot + 2 * CB2 + soff, g_wth + be, 16);
            cp16(slot + 3 * CB2 + soff, g_wtl + be, 16);
        }
        CP_COMMIT();
    };

    float acc[2][8][4];
    #pragma unroll
    for (int mi = 0; mi < 2; mi++)
        #pragma unroll
        for (int ni = 0; ni < 8; ni++)
            #pragma unroll
            for (int r = 0; r < 4; r++) acc[mi][ni][r] = 0.f;

    issue(0); issue(1); issue(2);
    for (int s = 0; s < nStages; s++) {
        CP_WAIT2();                 // stage s complete (3 groups outstanding max)
        __syncthreads();            // cross-warp visibility + ring-slot reuse safety
        issue(s + 3);               // overwrites slot of stage s-1 (all warps done with it)
        uint32_t slot = sb + (uint32_t)(s & (NSTAGE - 1)) * STAGE_B;
        mma_stage16(slot, slot + CB2, slot + 2 * CB2, slot + 3 * CB2, wm, wn, lane, acc);
    }
    __syncthreads();                // before smem reuse in epilogues

    // ---- epilogues ----
    if (mode == 0) {
        #pragma unroll
        for (int mi = 0; mi < 2; mi++) {
            int r0 = row0 + wm * 32 + mi * 16 + g, r1 = r0 + 8;
            #pragma unroll
            for (int ni = 0; ni < 8; ni++) {
                int coln = wn * 64 + ni * 8 + tg * 2;
                float2 bv = *reinterpret_cast<const float2*>(&bias[coln]);
                float2 o0, o1;
                o0.x = fmaxf(acc[mi][ni][0] + bv.x, 0.f);
                o0.y = fmaxf(acc[mi][ni][1] + bv.y, 0.f);
                o1.x = fmaxf(acc[mi][ni][2] + bv.x, 0.f);
                o1.y = fmaxf(acc[mi][ni][3] + bv.y, 0.f);
                if (r0 < N_NODES) *reinterpret_cast<float2*>(&outf[(size_t)r0 * C + coln]) = o0;
                if (r1 < N_NODES) *reinterpret_cast<float2*>(&outf[(size_t)r1 * C + coln]) = o1;
            }
        }
        return;
    }

    if (mode == 1) {
        #pragma unroll
        for (int ni = 0; ni < 8; ni++) {
            int coln = wn * 64 + ni * 8 + tg * 2;
            float2 bv = *reinterpret_cast<const float2*>(&bias[coln]);
            #pragma unroll
            for (int mi = 0; mi < 2; mi++) {
                acc[mi][ni][0] += bv.x; acc[mi][ni][1] += bv.y;
                acc[mi][ni][2] += bv.x; acc[mi][ni][3] += bv.y;
            }
        }
        float* red = (float*)smem;       // [128][2]
        float* invn = red + 256;         // [128]
        float ss0[2] = {0.f, 0.f}, ss1[2] = {0.f, 0.f};
        #pragma unroll
        for (int mi = 0; mi < 2; mi++)
            #pragma unroll
            for (int ni = 0; ni < 8; ni++) {
                ss0[mi] += acc[mi][ni][0] * acc[mi][ni][0] + acc[mi][ni][1] * acc[mi][ni][1];
                ss1[mi] += acc[mi][ni][2] * acc[mi][ni][2] + acc[mi][ni][3] * acc[mi][ni][3];
            }
        #pragma unroll
        for (int mi = 0; mi < 2; mi++) {
            ss0[mi] += __shfl_xor_sync(0xffffffffu, ss0[mi], 1);
            ss0[mi] += __shfl_xor_sync(0xffffffffu, ss0[mi], 2);
            ss1[mi] += __shfl_xor_sync(0xffffffffu, ss1[mi], 1);
            ss1[mi] += __shfl_xor_sync(0xffffffffu, ss1[mi], 2);
        }
        if (tg == 0) {
            #pragma unroll
            for (int mi = 0; mi < 2; mi++) {
                red[(wm * 32 + mi * 16 + g) * 2 + wn] = ss0[mi];
                red[(wm * 32 + mi * 16 + 8 + g) * 2 + wn] = ss1[mi];
            }
        }
        __syncthreads();
        if (t < 128) invn[t] = 1.f / fmaxf(sqrtf(red[t * 2] + red[t * 2 + 1]), L2_EPS);
        __syncthreads();
        #pragma unroll
        for (int mi = 0; mi < 2; mi++) {
            int lr0 = wm * 32 + mi * 16 + g;
            int r0 = row0 + lr0, r1 = r0 + 8;
            float i0 = invn[lr0], i1 = invn[lr0 + 8];
            #pragma unroll
            for (int ni = 0; ni < 8; ni++) {
                int coln = wn * 64 + ni * 8 + tg * 2;
                if (r0 < N_NODES) {
                    float2 o = *reinterpret_cast<float2*>(&outf[(size_t)r0 * C + coln]);
                    o.x += acc[mi][ni][0] * i0;
                    o.y += acc[mi][ni][1] * i0;
                    *reinterpret_cast<float2*>(&outf[(size_t)r0 * C + coln]) = o;
                }
                if (r1 < N_NODES) {
                    float2 o = *reinterpret_cast<float2*>(&outf[(size_t)r1 * C + coln]);
                    o.x += acc[mi][ni][2] * i1;
                    o.y += acc[mi][ni][3] * i1;
                    *reinterpret_cast<float2*>(&outf[(size_t)r1 * C + coln]) = o;
                }
            }
        }
        return;
    }

    const float sc = 1.f / 3.f;
    #pragma unroll
    for (int ni = 0; ni < 8; ni++) {
        int coln = wn * 64 + ni * 8 + tg * 2;
        float2 bv = *reinterpret_cast<const float2*>(&bias[coln]);
        #pragma unroll
        for (int mi = 0; mi < 2; mi++) {
            acc[mi][ni][0] = (acc[mi][ni][0] + bv.x) * sc;
            acc[mi][ni][1] = (acc[mi][ni][1] + bv.y) * sc;
            acc[mi][ni][2] = (acc[mi][ni][2] + bv.x) * sc;
            acc[mi][ni][3] = (acc[mi][ni][3] + bv.y) * sc;
            if (mode == 3) {
                acc[mi][ni][0] = fmaxf(acc[mi][ni][0], 0.f);
                acc[mi][ni][1] = fmaxf(acc[mi][ni][1], 0.f);
                acc[mi][ni][2] = fmaxf(acc[mi][ni][2], 0.f);
                acc[mi][ni][3] = fmaxf(acc[mi][ni][3], 0.f);
            }
        }
    }

    if (mode == 2) {
        #pragma unroll
        for (int mi = 0; mi < 2; mi++) {
            int r0 = row0 + wm * 32 + mi * 16 + g, r1 = r0 + 8;
            #pragma unroll
            for (int ni = 0; ni < 8; ni++) {
                int coln = wn * 64 + ni * 8 + tg * 2;
                if (r0 < N_NODES) {
                    float2 o; o.x = acc[mi][ni][0]; o.y = acc[mi][ni][1];
                    *reinterpret_cast<float2*>(&outf[(size_t)r0 * C + coln]) = o;
                }
                if (r1 < N_NODES) {
                    float2 o; o.x = acc[mi][ni][2]; o.y = acc[mi][ni][3];
                    *reinterpret_cast<float2*>(&outf[(size_t)r1 * C + coln]) = o;
                }
            }
        }
        return;
    }

    // mode 3: fused LayerNorm + h planes
    {
        float* red_s = (float*)smem;     // [128][2]
        float* red_q = red_s + 256;      // [128][2]
        float* rmean = red_q + 256;      // [128]
        float* rstdv = rmean + 128;      // [128]
        float s0[2] = {0.f, 0.f}, q0[2] = {0.f, 0.f};
        float s1[2] = {0.f, 0.f}, q1[2] = {0.f, 0.f};
        #pragma unroll
        for (int mi = 0; mi < 2; mi++)
            #pragma unroll
            for (int ni = 0; ni < 8; ni++) {
                s0[mi] += acc[mi][ni][0] + acc[mi][ni][1];
                q0[mi] += acc[mi][ni][0] * acc[mi][ni][0] + acc[mi][ni][1] * acc[mi][ni][1];
                s1[mi] += acc[mi][ni][2] + acc[mi][ni][3];
                q1[mi] += acc[mi][ni][2] * acc[mi][ni][2] + acc[mi][ni][3] * acc[mi][ni][3];
            }
        #pragma unroll
        for (int mi = 0; mi < 2; mi++) {
            s0[mi] += __shfl_xor_sync(0xffffffffu, s0[mi], 1);
            s0[mi] += __shfl_xor_sync(0xffffffffu, s0[mi], 2);
            q0[mi] += __shfl_xor_sync(0xffffffffu, q0[mi], 1);
            q0[mi] += __shfl_xor_sync(0xffffffffu, q0[mi], 2);
            s1[mi] += __shfl_xor_sync(0xffffffffu, s1[mi], 1);
            s1[mi] += __shfl_xor_sync(0xffffffffu, s1[mi], 2);
            q1[mi] += __shfl_xor_sync(0xffffffffu, q1[mi], 1);
            q1[mi] += __shfl_xor_sync(0xffffffffu, q1[mi], 2);
        }
        if (tg == 0) {
            #pragma unroll
            for (int mi = 0; mi < 2; mi++) {
                int lr = wm * 32 + mi * 16 + g;
                red_s[lr * 2 + wn] = s0[mi];
                red_q[lr * 2 + wn] = q0[mi];
                red_s[(lr + 8) * 2 + wn] = s1[mi];
                red_q[(lr + 8) * 2 + wn] = q1[mi];
            }
        }
        __syncthreads();
        if (t < 128) {
            float ssum = red_s[t * 2] + red_s[t * 2 + 1];
            float qsum = red_q[t * 2] + red_q[t * 2 + 1];
            float mean = ssum * (1.f / 128.f);
            float var = qsum * (1.f / 128.f) - mean * mean;
            rmean[t] = mean;
            rstdv[t] = rsqrtf(fmaxf(var, 0.f) + LN_EPS);
        }
        __syncthreads();
        #pragma unroll
        for (int mi = 0; mi < 2; mi++) {
            int lr0 = wm * 32 + mi * 16 + g;
            int r0 = row0 + lr0, r1 = r0 + 8;
            float m0v = rmean[lr0], d0 = rstdv[lr0];
            float m1v = rmean[lr0 + 8], d1 = rstdv[lr0 + 8];
            #pragma unroll
            for (int ni = 0; ni < 8; ni++) {
                int coln = wn * 64 + ni * 8 + tg * 2;
                float2 gv = *reinterpret_cast<const float2*>(&lng[coln]);
                float2 bb = *reinterpret_cast<const float2*>(&lnb[coln]);
                if (r0 < N_NODES) {
                    float2 o;
                    o.x = (acc[mi][ni][0] - m0v) * d0 * gv.x + bb.x;
                    o.y = (acc[mi][ni][1] - m0v) * d0 * gv.y + bb.y;
                    *reinterpret_cast<float2*>(&outf[(size_t)r0 * C + coln]) = o;
                    __nv_bfloat162 hh, ll;
                    split2(o.x, hh.x, ll.x); split2(o.y, hh.y, ll.y);
                    *reinterpret_cast<__nv_bfloat162*>(&g_hh[(size_t)r0 * C + coln]) = hh;
                    *reinterpret_cast<__nv_bfloat162*>(&g_hl[(size_t)r0 * C + coln]) = ll;
                }
                if (r1 < N_NODES) {
                    float2 o;
                    o.x = (acc[mi][ni][2] - m1v) * d1 * gv.x + bb.x;
                    o.y = (acc[mi][ni][3] - m1v) * d1 * gv.y + bb.y;
                    *reinterpret_cast<float2*>(&outf[(size_t)r1 * C + coln]) = o;
                    __nv_bfloat162 hh, ll;
                    split2(o.x, hh.x, ll.x); split2(o.y, hh.y, ll.y);
                    *reinterpret_cast<__nv_bfloat162*>(&g_hh[(size_t)r1 * C + coln]) = hh;
                    *reinterpret_cast<__nv_bfloat162*>(&g_hl[(size_t)r1 * C + coln]) = ll;
                }
            }
        }
    }
}

// ---------------- host orchestration ----------------
extern "C" void kernel_launch(void* const* d_in, const int* in_sizes, int n_in,
                              void* d_out, int out_size) {
    const float* x    = (const float*)d_in[0];
    const int*   edges = (const int*)d_in[1];
    const float* Wp   = (const float*)d_in[2];
    const float* bp   = (const float*)d_in[3];
    const float* Wl0  = (const float*)d_in[4];
    const float* bl0  = (const float*)d_in[5];
    const float* Wr0  = (const float*)d_in[6];
    const float* Wl   = (const float*)d_in[7];
    const float* bl   = (const float*)d_in[8];
    const float* Wr   = (const float*)d_in[9];
    const float* ln_g = (const float*)d_in[10];
    const float* ln_b = (const float*)d_in[11];
    float* out = (float*)d_out;

    void* p;
    float *msg0, *msg1, *msg2, *accb, *h, *bsum;
    __nv_bfloat16 *xh, *xl, *ah, *al, *hh, *hl;
    cudaGetSymbolAddress(&p, g_msg0); msg0 = (float*)p;
    cudaGetSymbolAddress(&p, g_msg1); msg1 = (float*)p;
    cudaGetSymbolAddress(&p, g_msg2); msg2 = (float*)p;
    cudaGetSymbolAddress(&p, g_accb); accb = (float*)p;
    cudaGetSymbolAddress(&p, g_h);    h = (float*)p;
    cudaGetSymbolAddress(&p, g_bsum); bsum = (float*)p;
    cudaGetSymbolAddress(&p, g_xh);   xh = (__nv_bfloat16*)p;
    cudaGetSymbolAddress(&p, g_xl);   xl = (__nv_bfloat16*)p;
    cudaGetSymbolAddress(&p, g_ah);   ah = (__nv_bfloat16*)p;
    cudaGetSymbolAddress(&p, g_al);   al = (__nv_bfloat16*)p;
    cudaGetSymbolAddress(&p, g_hh);   hh = (__nv_bfloat16*)p;
    cudaGetSymbolAddress(&p, g_hl);   hl = (__nv_bfloat16*)p;

    cudaFuncSetAttribute(k_gemm, cudaFuncAttributeMaxDynamicSharedMemorySize, SMEM_GEMM_BYTES);

    int nbScan = (N_NODES + 1023) / 1024;
    dim3 gScan(nbScan, ET);
    int gMma = (N_NODES + 127) / 128;
    int gWarp = (N_NODES * 32 + 255) / 256;

    // launches 1-3: weight + x prep
    k_wsum<<<(2 * C * C + 255) / 256, 256>>>(Wr, bl);
    k_wprep<<<dim3(16, 17), dim3(32, 8)>>>(Wp, Wl0, Wr0, Wl);
    k_xprep<<<(NC / 4 + 255) / 256, 256>>>(x);

    // launch 4 (ncu capture slot): projection GEMM, type 0
    k_gemm<<<gMma, 256, SMEM_GEMM_BYTES>>>(xh, xl, xh, xl, xh, xl, xh, xl,
                                           0, 0, 0, 0, 1, bp, ln_g, ln_b, msg0, 0);
    k_gemm<<<gMma, 256, SMEM_GEMM_BYTES>>>(xh, xl, xh, xl, xh, xl, xh, xl,
                                           1, 0, 0, 0, 1, bp + C, ln_g, ln_b, msg1, 0);
    k_gemm<<<gMma, 256, SMEM_GEMM_BYTES>>>(xh, xl, xh, xl, xh, xl, xh, xl,
                                           2, 0, 0, 0, 1, bp + 2 * C, ln_g, ln_b, msg2, 0);

    // CSR build + zero
    k_zero_int<<<(ET * N_NODES + 255) / 256, 256>>>();
    k_hist<<<(ET * N_EDGES + 255) / 256, 256>>>(edges);
    k_scan1<<<gScan, 1024>>>();
    k_scan2<<<1, 32>>>();
    k_scan3<<<gScan, 1024>>>();
    k_invdeg<<<(ET * N_NODES + 255) / 256, 256>>>();
    k_scatter<<<(ET * N_EDGES + 255) / 256, 256>>>(edges);
    k_zero_acc<<<(NC + 255) / 256, 256>>>();

    // layer 0: aggregate msgs -> agg planes; 3x dual GEMM (norm-accumulate); relu/3+LN -> h
    k_agg3<<<gWarp, 256>>>(msg0, msg1, msg2);
    for (int t = 0; t < 3; t++)
        k_gemm<<<gMma, 256, SMEM_GEMM_BYTES>>>(
            ah + (size_t)t * NC, al + (size_t)t * NC, xh, xl, xh, xl, xh, xl,
            3 + t, 6 + t, 0, 0, 2, bl0 + t * C, ln_g, ln_b, accb, 1);
    k_relu_ln_pl<<<gWarp, 256>>>(accb, ln_g, ln_b);

    // layer 1: h = LN(relu((Σ agg@Wl + h@ΣWr + Σb)/3)) + planes
    k_agg3<<<gWarp, 256>>>(h, h, h);
    k_gemm<<<gMma, 256, SMEM_GEMM_BYTES>>>(
        ah, al, ah + (size_t)NC, al + (size_t)NC, ah + 2 * (size_t)NC, al + 2 * (size_t)NC,
        hh, hl, 9, 10, 11, 15, 4, bsum, ln_g + C, ln_b + C, h, 3);

    // layer 2: out = (Σ agg@Wl + h@ΣWr + Σb)/3
    k_agg3<<<gWarp, 256>>>(h, h, h);
    k_gemm<<<gMma, 256, SMEM_GEMM_BYTES>>>(
        ah, al, ah + (size_t)NC, al + (size_t)NC, ah + 2 * (size_t)NC, al + 2 * (size_t)NC,
        hh, hl, 12, 13, 14, 16, 4, bsum + C, ln_g, ln_b, out, 2);
}

// round 12
// speedup vs baseline: 1.1246x; 1.1135x over previous
#include <cuda_runtime.h>
#include <cuda_bf16.h>
#include <cstdint>

#define N_NODES 100000
#define N_EDGES 500000
#define ET 3
#define C 128
#define NC (N_NODES * C)
#define LN_EPS 1e-5f
#define L2_EPS 1e-12f

// BK=16 stage geometry: plane = 128 rows x 24 halves (16 data + 8 pad)
#define P2 24
#define CH2 (128 * P2)             // halves per plane (3072)
#define CB2 (CH2 * 2)              // bytes per plane (6144)
#define STAGE_B (4 * CB2)          // bytes per stage (24576)
#define NSTAGE 4
#define SMEM_GEMM_BYTES (NSTAGE * STAGE_B)   // 98304; 2 CTAs/SM

// ---------------- scratch (static device globals; no allocation) ----------------
__device__ float g_msg0[NC];
__device__ float g_msg1[NC];
__device__ float g_msg2[NC];
__device__ float g_h[NC];
__device__ __align__(16) __nv_bfloat16 g_xh[NC];
__device__ __align__(16) __nv_bfloat16 g_xl[NC];
__device__ __align__(16) __nv_bfloat16 g_ah[3 * NC];   // agg planes hi
__device__ __align__(16) __nv_bfloat16 g_al[3 * NC];   // agg planes lo
__device__ __align__(16) __nv_bfloat16 g_hh[NC];       // h planes
__device__ __align__(16) __nv_bfloat16 g_hl[NC];
__device__ __align__(16) __nv_bfloat16 g_wth[17 * C * C];  // transposed+split weights [n][k]
__device__ __align__(16) __nv_bfloat16 g_wtl[17 * C * C];
__device__ float g_wsum[2 * C * C];
__device__ float g_bsum[2 * C];
__device__ float g_invdeg[ET * N_NODES];
__device__ int g_cnt[ET * N_NODES];
__device__ int g_cur[ET * N_NODES];
__device__ int g_rowptr[ET * (N_NODES + 1)];
__device__ int g_col[ET * N_EDGES];
__device__ int g_bofs[ET * 128];

// ---------------- helpers ----------------
__device__ __forceinline__ uint32_t smem_u32(const void* p) {
    uint32_t a;
    asm("{ .reg .u64 t; cvta.to.shared.u64 t, %1; cvt.u32.u64 %0, t; }" : "=r"(a) : "l"(p));
    return a;
}
__device__ __forceinline__ void cp16(uint32_t dst, const void* src, int srcsize) {
    asm volatile("cp.async.cg.shared.global [%0], [%1], 16, %2;"
                 :: "r"(dst), "l"(src), "r"(srcsize));
}
#define CP_COMMIT() asm volatile("cp.async.commit_group;" ::: "memory")
#define CP_WAIT2()  asm volatile("cp.async.wait_group 2;" ::: "memory")

__device__ __forceinline__ void split2(float x, __nv_bfloat16& hi, __nv_bfloat16& lo) {
    hi = __float2bfloat16_rn(x);
    lo = __float2bfloat16_rn(x - __bfloat162float(hi));
}
__device__ __forceinline__ void mma_bf16(float* d, const uint32_t* a, uint32_t b0, uint32_t b1) {
    asm volatile(
        "mma.sync.aligned.m16n8k16.row.col.f32.bf16.bf16.f32 "
        "{%0,%1,%2,%3}, {%4,%5,%6,%7}, {%8,%9}, {%0,%1,%2,%3};"
        : "+f"(d[0]), "+f"(d[1]), "+f"(d[2]), "+f"(d[3])
        : "r"(a[0]), "r"(a[1]), "r"(a[2]), "r"(a[3]), "r"(b0), "r"(b1));
}
__device__ __forceinline__ void ldsm4(uint32_t a, uint32_t& r0, uint32_t& r1,
                                      uint32_t& r2, uint32_t& r3) {
    asm volatile("ldmatrix.sync.aligned.m8n8.x4.shared.b16 {%0,%1,%2,%3}, [%4];"
                 : "=r"(r0), "=r"(r1), "=r"(r2), "=r"(r3) : "r"(a));
}

// ---------------- CSR build ----------------
__global__ void k_zero_int() {
    int i = blockIdx.x * blockDim.x + threadIdx.x;
    if (i < ET * N_NODES) { g_cnt[i] = 0; g_cur[i] = 0; }
}
__global__ void k_hist(const int* __restrict__ edges) {
    int i = blockIdx.x * blockDim.x + threadIdx.x;
    if (i >= ET * N_EDGES) return;
    int t = i / N_EDGES, e = i - t * N_EDGES;
    int dst = edges[(t * 2 + 1) * N_EDGES + e];
    atomicAdd(&g_cnt[t * N_NODES + dst], 1);
}
__global__ void k_scan1() {
    int t = blockIdx.y;
    int i = blockIdx.x * 1024 + threadIdx.x;
    __shared__ int sm[1024];
    int v = (i < N_NODES) ? g_cnt[t * N_NODES + i] : 0;
    if (i < N_NODES)
        g_invdeg[t * N_NODES + i] = 1.0f / (float)(v > 1 ? v : 1);   // fused invdeg
    sm[threadIdx.x] = v;
    __syncthreads();
    for (int off = 1; off < 1024; off <<= 1) {
        int add = (threadIdx.x >= off) ? sm[threadIdx.x - off] : 0;
        __syncthreads();
        sm[threadIdx.x] += add;
        __syncthreads();
    }
    if (i < N_NODES) g_rowptr[t * (N_NODES + 1) + i] = sm[threadIdx.x] - v;
    if (threadIdx.x == 1023) g_bofs[t * 128 + blockIdx.x] = sm[1023];
}
__global__ void k_scan2() {
    int t = threadIdx.x;
    if (t >= ET) return;
    int nb = (N_NODES + 1023) / 1024;
    int run = 0;
    for (int b = 0; b < nb; b++) { int v = g_bofs[t * 128 + b]; g_bofs[t * 128 + b] = run; run += v; }
    g_rowptr[t * (N_NODES + 1) + N_NODES] = run;
}
__global__ void k_scan3() {
    int t = blockIdx.y;
    int i = blockIdx.x * 1024 + threadIdx.x;
    if (i < N_NODES) g_rowptr[t * (N_NODES + 1) + i] += g_bofs[t * 128 + blockIdx.x];
}
__global__ void k_scatter(const int* __restrict__ edges) {
    int i = blockIdx.x * blockDim.x + threadIdx.x;
    if (i >= ET * N_EDGES) return;
    int t = i / N_EDGES, e = i - t * N_EDGES;
    int src = edges[t * 2 * N_EDGES + e];
    int dst = edges[(t * 2 + 1) * N_EDGES + e];
    int pos = g_rowptr[t * (N_NODES + 1) + dst] + atomicAdd(&g_cur[t * N_NODES + dst], 1);
    g_col[t * N_EDGES + pos] = src;
}

// ---------------- weight pre-sum + prep ----------------
__global__ void k_wsum(const float* __restrict__ Wr, const float* __restrict__ bl) {
    int i = blockIdx.x * blockDim.x + threadIdx.x;
    if (i < 2 * C * C) {
        int l = i / (C * C), idx = i - l * (C * C);
        g_wsum[i] = Wr[(l * 3 + 0) * C * C + idx] + Wr[(l * 3 + 1) * C * C + idx]
                  + Wr[(l * 3 + 2) * C * C + idx];
    }
    if (i < 2 * C) {
        int l = i / C, cc = i - l * C;
        g_bsum[i] = bl[(l * 3 + 0) * C + cc] + bl[(l * 3 + 1) * C + cc] + bl[(l * 3 + 2) * C + cc];
    }
}
// mats: 0-2 Wp, 3-5 Wl0, 6-8 Wr0, 9-14 Wl, 15-16 wsum.  out[m][n][k] = split(W[m][k][n])
__global__ void k_wprep(const float* __restrict__ Wp, const float* __restrict__ Wl0,
                        const float* __restrict__ Wr0, const float* __restrict__ Wl) {
    int m = blockIdx.y;
    const float* src;
    if (m < 3) src = Wp + (size_t)m * C * C;
    else if (m < 6) src = Wl0 + (size_t)(m - 3) * C * C;
    else if (m < 9) src = Wr0 + (size_t)(m - 6) * C * C;
    else if (m < 15) src = Wl + (size_t)(m - 9) * C * C;
    else src = g_wsum + (size_t)(m - 15) * C * C;
    __shared__ float tile[32][33];
    int txt = (blockIdx.x & 3) * 32, tyt = (blockIdx.x >> 2) * 32;
    int tx = threadIdx.x, ty = threadIdx.y;
    #pragma unroll
    for (int i = 0; i < 4; i++)
        tile[ty + i * 8][tx] = src[(size_t)(tyt + ty + i * 8) * C + txt + tx];
    __syncthreads();
    #pragma unroll
    for (int i = 0; i < 4; i++) {
        int n = txt + ty + i * 8, k = tyt + tx;
        float v = tile[tx][ty + i * 8];
        __nv_bfloat16 hi, lo; split2(v, hi, lo);
        g_wth[(size_t)m * C * C + n * C + k] = hi;
        g_wtl[(size_t)m * C * C + n * C + k] = lo;
    }
}
// split x once into bf16 planes
__global__ void k_xprep(const float* __restrict__ x) {
    int i = blockIdx.x * blockDim.x + threadIdx.x;
    if (i * 4 >= NC) return;
    float4 v = *reinterpret_cast<const float4*>(&x[(size_t)i * 4]);
    __nv_bfloat162 hA, hB, lA, lB;
    split2(v.x, hA.x, lA.x); split2(v.y, hA.y, lA.y);
    split2(v.z, hB.x, lB.x); split2(v.w, hB.y, lB.y);
    uint2 uh, ul;
    uh.x = *reinterpret_cast<uint32_t*>(&hA); uh.y = *reinterpret_cast<uint32_t*>(&hB);
    ul.x = *reinterpret_cast<uint32_t*>(&lA); ul.y = *reinterpret_cast<uint32_t*>(&lB);
    *reinterpret_cast<uint2*>(&g_xh[(size_t)i * 4]) = uh;
    *reinterpret_cast<uint2*>(&g_xl[(size_t)i * 4]) = ul;
}

// ---------------- mean aggregation: grid.y = edge type (3x warp parallelism) ----------------
__global__ void k_agg3(const float* __restrict__ f0, const float* __restrict__ f1,
                       const float* __restrict__ f2) {
    int t = blockIdx.y;
    int w = (blockIdx.x * blockDim.x + threadIdx.x) >> 5;
    int lane = threadIdx.x & 31;
    if (w >= N_NODES) return;
    const float* feat = (t == 0) ? f0 : (t == 1) ? f1 : f2;
    const int* rp = &g_rowptr[t * (N_NODES + 1)];
    int s = rp[w], e = rp[w + 1];
    const int* col = &g_col[t * N_EDGES];
    float4 acc = make_float4(0.f, 0.f, 0.f, 0.f);
    int j = s;
    for (; j + 3 < e; j += 4) {
        int s0 = col[j], s1 = col[j + 1], s2 = col[j + 2], s3 = col[j + 3];
        float4 v0 = *reinterpret_cast<const float4*>(&feat[(size_t)s0 * C + lane * 4]);
        float4 v1 = *reinterpret_cast<const float4*>(&feat[(size_t)s1 * C + lane * 4]);
        float4 v2 = *reinterpret_cast<const float4*>(&feat[(size_t)s2 * C + lane * 4]);
        float4 v3 = *reinterpret_cast<const float4*>(&feat[(size_t)s3 * C + lane * 4]);
        acc.x += v0.x; acc.y += v0.y; acc.z += v0.z; acc.w += v0.w;
        acc.x += v1.x; acc.y += v1.y; acc.z += v1.z; acc.w += v1.w;
        acc.x += v2.x; acc.y += v2.y; acc.z += v2.z; acc.w += v2.w;
        acc.x += v3.x; acc.y += v3.y; acc.z += v3.z; acc.w += v3.w;
    }
    for (; j < e; j++) {
        int s0 = col[j];
        float4 v0 = *reinterpret_cast<const float4*>(&feat[(size_t)s0 * C + lane * 4]);
        acc.x += v0.x; acc.y += v0.y; acc.z += v0.z; acc.w += v0.w;
    }
    float inv = g_invdeg[t * N_NODES + w];
    acc.x *= inv; acc.y *= inv; acc.z *= inv; acc.w *= inv;
    __nv_bfloat162 hA, hB, lA, lB;
    split2(acc.x, hA.x, lA.x); split2(acc.y, hA.y, lA.y);
    split2(acc.z, hB.x, lB.x); split2(acc.w, hB.y, lB.y);
    size_t off = (size_t)t * NC + (size_t)w * C + lane * 4;
    uint2 uh, ul;
    uh.x = *reinterpret_cast<uint32_t*>(&hA); uh.y = *reinterpret_cast<uint32_t*>(&hB);
    ul.x = *reinterpret_cast<uint32_t*>(&lA); ul.y = *reinterpret_cast<uint32_t*>(&lB);
    *reinterpret_cast<uint2*>(&g_ah[off]) = uh;
    *reinterpret_cast<uint2*>(&g_al[off]) = ul;
}

// ---------------- sum3 + relu/3 + LayerNorm -> h fp32 + planes ----------------
__global__ void k_relu_ln3(const float* __restrict__ i0, const float* __restrict__ i1,
                           const float* __restrict__ i2,
                           const float* __restrict__ g, const float* __restrict__ b) {
    int w = (blockIdx.x * blockDim.x + threadIdx.x) >> 5;
    int lane = threadIdx.x & 31;
    if (w >= N_NODES) return;
    size_t off0 = (size_t)w * C + lane * 4;
    float4 a0 = *reinterpret_cast<const float4*>(&i0[off0]);
    float4 a1 = *reinterpret_cast<const float4*>(&i1[off0]);
    float4 a2 = *reinterpret_cast<const float4*>(&i2[off0]);
    float4 v;
    v.x = (a0.x + a1.x) + a2.x;
    v.y = (a0.y + a1.y) + a2.y;
    v.z = (a0.z + a1.z) + a2.z;
    v.w = (a0.w + a1.w) + a2.w;
    v.x = fmaxf(v.x * (1.f / 3.f), 0.f);
    v.y = fmaxf(v.y * (1.f / 3.f), 0.f);
    v.z = fmaxf(v.z * (1.f / 3.f), 0.f);
    v.w = fmaxf(v.w * (1.f / 3.f), 0.f);
    float s = v.x + v.y + v.z + v.w;
    #pragma unroll
    for (int off = 16; off > 0; off >>= 1) s += __shfl_xor_sync(0xffffffffu, s, off);
    float mean = s * (1.f / 128.f);
    float dx = v.x - mean, dy = v.y - mean, dz = v.z - mean, dw = v.w - mean;
    float ss = dx * dx + dy * dy + dz * dz + dw * dw;
    #pragma unroll
    for (int off = 16; off > 0; off >>= 1) ss += __shfl_xor_sync(0xffffffffu, ss, off);
    float rstd = rsqrtf(ss * (1.f / 128.f) + LN_EPS);
    float4 gg = *reinterpret_cast<const float4*>(&g[lane * 4]);
    float4 bb = *reinterpret_cast<const float4*>(&b[lane * 4]);
    float4 o;
    o.x = dx * rstd * gg.x + bb.x;
    o.y = dy * rstd * gg.y + bb.y;
    o.z = dz * rstd * gg.z + bb.z;
    o.w = dw * rstd * gg.w + bb.w;
    *reinterpret_cast<float4*>(&g_h[off0]) = o;
    __nv_bfloat162 hA, hB, lA, lB;
    split2(o.x, hA.x, lA.x); split2(o.y, hA.y, lA.y);
    split2(o.z, hB.x, lB.x); split2(o.w, hB.y, lB.y);
    uint2 uh, ul;
    uh.x = *reinterpret_cast<uint32_t*>(&hA); uh.y = *reinterpret_cast<uint32_t*>(&hB);
    ul.x = *reinterpret_cast<uint32_t*>(&lA); ul.y = *reinterpret_cast<uint32_t*>(&lB);
    *reinterpret_cast<uint2*>(&g_hh[off0]) = uh;
    *reinterpret_cast<uint2*>(&g_hl[off0]) = ul;
}

// ---------------- one 128x128x16 stage: ldmatrix + dependency-spread passes ----------------
__device__ __forceinline__ void mma_stage16(
    uint32_t Ahi, uint32_t Alo, uint32_t Bhi, uint32_t Blo,
    int wm, int wn, int lane, float (*acc)[8][4])
{
    int aRow = lane & 15;
    uint32_t aColB = ((lane >> 4) & 1) * 16;
    int bRow = (lane & 7) | (((lane >> 4) & 1) << 3);
    uint32_t bColB = ((lane >> 3) & 1) * 16;
    uint32_t aoff0 = (uint32_t)((wm * 32 + aRow) * 48) + aColB;
    uint32_t aoff1 = aoff0 + 16 * 48;
    uint32_t boff = (uint32_t)((wn * 64 + bRow) * 48) + bColB;
    uint32_t ah[2][4], al[2][4];
    ldsm4(Ahi + aoff0, ah[0][0], ah[0][1], ah[0][2], ah[0][3]);
    ldsm4(Ahi + aoff1, ah[1][0], ah[1][1], ah[1][2], ah[1][3]);
    ldsm4(Alo + aoff0, al[0][0], al[0][1], al[0][2], al[0][3]);
    ldsm4(Alo + aoff1, al[1][0], al[1][1], al[1][2], al[1][3]);
    #pragma unroll
    for (int q = 0; q < 2; q++) {
        uint32_t nq = boff + (uint32_t)(q * 32 * 48);
        uint32_t bh[4][2], bl[4][2];
        ldsm4(Bhi + nq,           bh[0][0], bh[0][1], bh[1][0], bh[1][1]);
        ldsm4(Bhi + nq + 16 * 48, bh[2][0], bh[2][1], bh[3][0], bh[3][1]);
        ldsm4(Blo + nq,           bl[0][0], bl[0][1], bl[1][0], bl[1][1]);
        ldsm4(Blo + nq + 16 * 48, bl[2][0], bl[2][1], bl[3][0], bl[3][1]);
        #pragma unroll
        for (int j = 0; j < 4; j++) {
            mma_bf16(acc[0][q * 4 + j], ah[0], bh[j][0], bh[j][1]);
            mma_bf16(acc[1][q * 4 + j], ah[1], bh[j][0], bh[j][1]);
        }
        #pragma unroll
        for (int j = 0; j < 4; j++) {
            mma_bf16(acc[0][q * 4 + j], ah[0], bl[j][0], bl[j][1]);
            mma_bf16(acc[1][q * 4 + j], ah[1], bl[j][0], bl[j][1]);
        }
        #pragma unroll
        for (int j = 0; j < 4; j++) {
            mma_bf16(acc[0][q * 4 + j], al[0], bh[j][0], bh[j][1]);
            mma_bf16(acc[1][q * 4 + j], al[1], bh[j][0], bh[j][1]);
        }
    }
}

// ---------------- unified streaming GEMM (cp.async 4-deep ring, 1 sync/stage) ----------------
// batched over blockIdx.y = tt: mats += tt, bias += tt*C, A chunk0 += tt*aStride0,
// out = {o0,o1,o2}[tt].  Epilogue by mode:
//  0: out = relu(acc+bias)
//  1: out = L2rownorm(acc+bias)           (write, no RMW)
//  2: out = (acc+bias)/3
//  3: out = LN(relu((acc+bias)/3)) + write g_hh/g_hl planes
__global__ __launch_bounds__(256, 2) void k_gemm(
    const __nv_bfloat16* __restrict__ A0h, const __nv_bfloat16* __restrict__ A0l,
    const __nv_bfloat16* __restrict__ A1h, const __nv_bfloat16* __restrict__ A1l,
    const __nv_bfloat16* __restrict__ A2h, const __nv_bfloat16* __restrict__ A2l,
    const __nv_bfloat16* __restrict__ A3h, const __nv_bfloat16* __restrict__ A3l,
    int m0, int m1, int m2, int m3, int nChunks, int aStride0,
    const float* __restrict__ bias, const float* __restrict__ lng,
    const float* __restrict__ lnb,
    float* __restrict__ o0, float* __restrict__ o1, float* __restrict__ o2, int mode)
{
    extern __shared__ __align__(16) char smem[];
    uint32_t sb = smem_u32(smem);
    int tt = blockIdx.y;
    int t = threadIdx.x, lane = t & 31, wid = t >> 5;
    int g = lane >> 2, tg = lane & 3;
    int wm = wid & 3, wn = wid >> 2;
    int row0 = blockIdx.x * 128;
    int ar = t >> 1, sel = t & 1;
    uint32_t soff = (uint32_t)(ar * 48 + sel * 16);
    int gr = row0 + ar;
    bool rvalid = gr < N_NODES;
    int grc = rvalid ? gr : (N_NODES - 1);
    int ssz = rvalid ? 16 : 0;

    const __nv_bfloat16* Ah[4] = {A0h + (size_t)tt * aStride0, A1h, A2h, A3h};
    const __nv_bfloat16* Al[4] = {A0l + (size_t)tt * aStride0, A1l, A2l, A3l};
    int mats[4] = {m0 + tt, m1 + tt, m2 + tt, m3 + tt};
    bias += tt * C;
    float* outf = (tt == 0) ? o0 : (tt == 1) ? o1 : o2;
    int nStages = nChunks * 8;     // K chunks of 16

    auto issue = [&](int s) {
        if (s < nStages) {
            uint32_t slot = sb + (uint32_t)(s & (NSTAGE - 1)) * STAGE_B;
            int c = s >> 3, kc = (s & 7) * 16;
            size_t ae = (size_t)grc * C + kc + sel * 8;
            cp16(slot + soff, Ah[c] + ae, ssz);
            cp16(slot + CB2 + soff, Al[c] + ae, ssz);
            size_t be = (size_t)mats[c] * C * C + (size_t)ar * C + kc + sel * 8;
            cp16(slot + 2 * CB2 + soff, g_wth + be, 16);
            cp16(slot + 3 * CB2 + soff, g_wtl + be, 16);
        }
        CP_COMMIT();
    };

    float acc[2][8][4];
    #pragma unroll
    for (int mi = 0; mi < 2; mi++)
        #pragma unroll
        for (int ni = 0; ni < 8; ni++)
            #pragma unroll
            for (int r = 0; r < 4; r++) acc[mi][ni][r] = 0.f;

    issue(0); issue(1); issue(2);
    for (int s = 0; s < nStages; s++) {
        CP_WAIT2();
        __syncthreads();
        issue(s + 3);
        uint32_t slot = sb + (uint32_t)(s & (NSTAGE - 1)) * STAGE_B;
        mma_stage16(slot, slot + CB2, slot + 2 * CB2, slot + 3 * CB2, wm, wn, lane, acc);
    }
    __syncthreads();

    // ---- epilogues ----
    if (mode == 0) {
        #pragma unroll
        for (int mi = 0; mi < 2; mi++) {
            int r0 = row0 + wm * 32 + mi * 16 + g, r1 = r0 + 8;
            #pragma unroll
            for (int ni = 0; ni < 8; ni++) {
                int coln = wn * 64 + ni * 8 + tg * 2;
                float2 bv = *reinterpret_cast<const float2*>(&bias[coln]);
                float2 u0, u1;
                u0.x = fmaxf(acc[mi][ni][0] + bv.x, 0.f);
                u0.y = fmaxf(acc[mi][ni][1] + bv.y, 0.f);
                u1.x = fmaxf(acc[mi][ni][2] + bv.x, 0.f);
                u1.y = fmaxf(acc[mi][ni][3] + bv.y, 0.f);
                if (r0 < N_NODES) *reinterpret_cast<float2*>(&outf[(size_t)r0 * C + coln]) = u0;
                if (r1 < N_NODES) *reinterpret_cast<float2*>(&outf[(size_t)r1 * C + coln]) = u1;
            }
        }
        return;
    }

    if (mode == 1) {
        #pragma unroll
        for (int ni = 0; ni < 8; ni++) {
            int coln = wn * 64 + ni * 8 + tg * 2;
            float2 bv = *reinterpret_cast<const float2*>(&bias[coln]);
            #pragma unroll
            for (int mi = 0; mi < 2; mi++) {
                acc[mi][ni][0] += bv.x; acc[mi][ni][1] += bv.y;
                acc[mi][ni][2] += bv.x; acc[mi][ni][3] += bv.y;
            }
        }
        float* red = (float*)smem;       // [128][2]
        float* invn = red + 256;         // [128]
        float ss0[2] = {0.f, 0.f}, ss1[2] = {0.f, 0.f};
        #pragma unroll
        for (int mi = 0; mi < 2; mi++)
            #pragma unroll
            for (int ni = 0; ni < 8; ni++) {
                ss0[mi] += acc[mi][ni][0] * acc[mi][ni][0] + acc[mi][ni][1] * acc[mi][ni][1];
                ss1[mi] += acc[mi][ni][2] * acc[mi][ni][2] + acc[mi][ni][3] * acc[mi][ni][3];
            }
        #pragma unroll
        for (int mi = 0; mi < 2; mi++) {
            ss0[mi] += __shfl_xor_sync(0xffffffffu, ss0[mi], 1);
            ss0[mi] += __shfl_xor_sync(0xffffffffu, ss0[mi], 2);
            ss1[mi] += __shfl_xor_sync(0xffffffffu, ss1[mi], 1);
            ss1[mi] += __shfl_xor_sync(0xffffffffu, ss1[mi], 2);
        }
        if (tg == 0) {
            #pragma unroll
            for (int mi = 0; mi < 2; mi++) {
                red[(wm * 32 + mi * 16 + g) * 2 + wn] = ss0[mi];
                red[(wm * 32 + mi * 16 + 8 + g) * 2 + wn] = ss1[mi];
            }
        }
        __syncthreads();
        if (t < 128) invn[t] = 1.f / fmaxf(sqrtf(red[t * 2] + red[t * 2 + 1]), L2_EPS);
        __syncthreads();
        #pragma unroll
        for (int mi = 0; mi < 2; mi++) {
            int lr0 = wm * 32 + mi * 16 + g;
            int r0 = row0 + lr0, r1 = r0 + 8;
            float i0 = invn[lr0], i1 = invn[lr0 + 8];
            #pragma unroll
            for (int ni = 0; ni < 8; ni++) {
                int coln = wn * 64 + ni * 8 + tg * 2;
                if (r0 < N_NODES) {
                    float2 o;
                    o.x = acc[mi][ni][0] * i0;
                    o.y = acc[mi][ni][1] * i0;
                    *reinterpret_cast<float2*>(&outf[(size_t)r0 * C + coln]) = o;
                }
                if (r1 < N_NODES) {
                    float2 o;
                    o.x = acc[mi][ni][2] * i1;
                    o.y = acc[mi][ni][3] * i1;
                    *reinterpret_cast<float2*>(&outf[(size_t)r1 * C + coln]) = o;
                }
            }
        }
        return;
    }

    const float sc = 1.f / 3.f;
    #pragma unroll
    for (int ni = 0; ni < 8; ni++) {
        int coln = wn * 64 + ni * 8 + tg * 2;
        float2 bv = *reinterpret_cast<const float2*>(&bias[coln]);
        #pragma unroll
        for (int mi = 0; mi < 2; mi++) {
            acc[mi][ni][0] = (acc[mi][ni][0] + bv.x) * sc;
            acc[mi][ni][1] = (acc[mi][ni][1] + bv.y) * sc;
            acc[mi][ni][2] = (acc[mi][ni][2] + bv.x) * sc;
            acc[mi][ni][3] = (acc[mi][ni][3] + bv.y) * sc;
            if (mode == 3) {
                acc[mi][ni][0] = fmaxf(acc[mi][ni][0], 0.f);
                acc[mi][ni][1] = fmaxf(acc[mi][ni][1], 0.f);
                acc[mi][ni][2] = fmaxf(acc[mi][ni][2], 0.f);
                acc[mi][ni][3] = fmaxf(acc[mi][ni][3], 0.f);
            }
        }
    }

    if (mode == 2) {
        #pragma unroll
        for (int mi = 0; mi < 2; mi++) {
            int r0 = row0 + wm * 32 + mi * 16 + g, r1 = r0 + 8;
            #pragma unroll
            for (int ni = 0; ni < 8; ni++) {
                int coln = wn * 64 + ni * 8 + tg * 2;
                if (r0 < N_NODES) {
                    float2 o; o.x = acc[mi][ni][0]; o.y = acc[mi][ni][1];
                    *reinterpret_cast<float2*>(&outf[(size_t)r0 * C + coln]) = o;
                }
                if (r1 < N_NODES) {
                    float2 o; o.x = acc[mi][ni][2]; o.y = acc[mi][ni][3];
                    *reinterpret_cast<float2*>(&outf[(size_t)r1 * C + coln]) = o;
                }
            }
        }
        return;
    }

    // mode 3: fused LayerNorm + h planes
    {
        float* red_s = (float*)smem;     // [128][2]
        float* red_q = red_s + 256;      // [128][2]
        float* rmean = red_q + 256;      // [128]
        float* rstdv = rmean + 128;      // [128]
        float s0[2] = {0.f, 0.f}, q0[2] = {0.f, 0.f};
        float s1[2] = {0.f, 0.f}, q1[2] = {0.f, 0.f};
        #pragma unroll
        for (int mi = 0; mi < 2; mi++)
            #pragma unroll
            for (int ni = 0; ni < 8; ni++) {
                s0[mi] += acc[mi][ni][0] + acc[mi][ni][1];
                q0[mi] += acc[mi][ni][0] * acc[mi][ni][0] + acc[mi][ni][1] * acc[mi][ni][1];
                s1[mi] += acc[mi][ni][2] + acc[mi][ni][3];
                q1[mi] += acc[mi][ni][2] * acc[mi][ni][2] + acc[mi][ni][3] * acc[mi][ni][3];
            }
        #pragma unroll
        for (int mi = 0; mi < 2; mi++) {
            s0[mi] += __shfl_xor_sync(0xffffffffu, s0[mi], 1);
            s0[mi] += __shfl_xor_sync(0xffffffffu, s0[mi], 2);
            q0[mi] += __shfl_xor_sync(0xffffffffu, q0[mi], 1);
            q0[mi] += __shfl_xor_sync(0xffffffffu, q0[mi], 2);
            s1[mi] += __shfl_xor_sync(0xffffffffu, s1[mi], 1);
            s1[mi] += __shfl_xor_sync(0xffffffffu, s1[mi], 2);
            q1[mi] += __shfl_xor_sync(0xffffffffu, q1[mi], 1);
            q1[mi] += __shfl_xor_sync(0xffffffffu, q1[mi], 2);
        }
        if (tg == 0) {
            #pragma unroll
            for (int mi = 0; mi < 2; mi++) {
                int lr = wm * 32 + mi * 16 + g;
                red_s[lr * 2 + wn] = s0[mi];
                red_q[lr * 2 + wn] = q0[mi];
                red_s[(lr + 8) * 2 + wn] = s1[mi];
                red_q[(lr + 8) * 2 + wn] = q1[mi];
            }
        }
        __syncthreads();
        if (t < 128) {
            float ssum = red_s[t * 2] + red_s[t * 2 + 1];
            float qsum = red_q[t * 2] + red_q[t * 2 + 1];
            float mean = ssum * (1.f / 128.f);
            float var = qsum * (1.f / 128.f) - mean * mean;
            rmean[t] = mean;
            rstdv[t] = rsqrtf(fmaxf(var, 0.f) + LN_EPS);
        }
        __syncthreads();
        #pragma unroll
        for (int mi = 0; mi < 2; mi++) {
            int lr0 = wm * 32 + mi * 16 + g;
            int r0 = row0 + lr0, r1 = r0 + 8;
            float m0v = rmean[lr0], d0 = rstdv[lr0];
            float m1v = rmean[lr0 + 8], d1 = rstdv[lr0 + 8];
            #pragma unroll
            for (int ni = 0; ni < 8; ni++) {
                int coln = wn * 64 + ni * 8 + tg * 2;
                float2 gv = *reinterpret_cast<const float2*>(&lng[coln]);
                float2 bb = *reinterpret_cast<const float2*>(&lnb[coln]);
                if (r0 < N_NODES) {
                    float2 o;
                    o.x = (acc[mi][ni][0] - m0v) * d0 * gv.x + bb.x;
                    o.y = (acc[mi][ni][1] - m0v) * d0 * gv.y + bb.y;
                    *reinterpret_cast<float2*>(&outf[(size_t)r0 * C + coln]) = o;
                    __nv_bfloat162 hh, ll;
                    split2(o.x, hh.x, ll.x); split2(o.y, hh.y, ll.y);
                    *reinterpret_cast<__nv_bfloat162*>(&g_hh[(size_t)r0 * C + coln]) = hh;
                    *reinterpret_cast<__nv_bfloat162*>(&g_hl[(size_t)r0 * C + coln]) = ll;
                }
                if (r1 < N_NODES) {
                    float2 o;
                    o.x = (acc[mi][ni][2] - m1v) * d1 * gv.x + bb.x;
                    o.y = (acc[mi][ni][3] - m1v) * d1 * gv.y + bb.y;
                    *reinterpret_cast<float2*>(&outf[(size_t)r1 * C + coln]) = o;
                    __nv_bfloat162 hh, ll;
                    split2(o.x, hh.x, ll.x); split2(o.y, hh.y, ll.y);
                    *reinterpret_cast<__nv_bfloat162*>(&g_hh[(size_t)r1 * C + coln]) = hh;
                    *reinterpret_cast<__nv_bfloat162*>(&g_hl[(size_t)r1 * C + coln]) = ll;
                }
            }
        }
    }
}

// ---------------- host orchestration ----------------
extern "C" void kernel_launch(void* const* d_in, const int* in_sizes, int n_in,
                              void* d_out, int out_size) {
    const float* x    = (const float*)d_in[0];
    const int*   edges = (const int*)d_in[1];
    const float* Wp   = (const float*)d_in[2];
    const float* bp   = (const float*)d_in[3];
    const float* Wl0  = (const float*)d_in[4];
    const float* bl0  = (const float*)d_in[5];
    const float* Wr0  = (const float*)d_in[6];
    const float* Wl   = (const float*)d_in[7];
    const float* bl   = (const float*)d_in[8];
    const float* Wr   = (const float*)d_in[9];
    const float* ln_g = (const float*)d_in[10];
    const float* ln_b = (const float*)d_in[11];
    float* out = (float*)d_out;

    void* p;
    float *msg0, *msg1, *msg2, *h, *bsum;
    __nv_bfloat16 *xh, *xl, *ah, *al, *hh, *hl;
    cudaGetSymbolAddress(&p, g_msg0); msg0 = (float*)p;
    cudaGetSymbolAddress(&p, g_msg1); msg1 = (float*)p;
    cudaGetSymbolAddress(&p, g_msg2); msg2 = (float*)p;
    cudaGetSymbolAddress(&p, g_h);    h = (float*)p;
    cudaGetSymbolAddress(&p, g_bsum); bsum = (float*)p;
    cudaGetSymbolAddress(&p, g_xh);   xh = (__nv_bfloat16*)p;
    cudaGetSymbolAddress(&p, g_xl);   xl = (__nv_bfloat16*)p;
    cudaGetSymbolAddress(&p, g_ah);   ah = (__nv_bfloat16*)p;
    cudaGetSymbolAddress(&p, g_al);   al = (__nv_bfloat16*)p;
    cudaGetSymbolAddress(&p, g_hh);   hh = (__nv_bfloat16*)p;
    cudaGetSymbolAddress(&p, g_hl);   hl = (__nv_bfloat16*)p;

    cudaFuncSetAttribute(k_gemm, cudaFuncAttributeMaxDynamicSharedMemorySize, SMEM_GEMM_BYTES);

    int nbScan = (N_NODES + 1023) / 1024;
    dim3 gScan(nbScan, ET);
    int gMma = (N_NODES + 127) / 128;
    int gWarp = (N_NODES * 32 + 255) / 256;

    // launches 1-3: weight + x prep
    k_wsum<<<(2 * C * C + 255) / 256, 256>>>(Wr, bl);
    k_wprep<<<dim3(16, 17), dim3(32, 8)>>>(Wp, Wl0, Wr0, Wl);
    k_xprep<<<(NC / 4 + 255) / 256, 256>>>(x);

    // launch 4 (ncu capture slot): ALL THREE projections in one batched launch
    k_gemm<<<dim3(gMma, 3), 256, SMEM_GEMM_BYTES>>>(
        xh, xl, xh, xl, xh, xl, xh, xl,
        0, 0, 0, 0, 1, 0, bp, ln_g, ln_b, msg0, msg1, msg2, 0);

    // CSR build
    k_zero_int<<<(ET * N_NODES + 255) / 256, 256>>>();
    k_hist<<<(ET * N_EDGES + 255) / 256, 256>>>(edges);
    k_scan1<<<gScan, 1024>>>();
    k_scan2<<<1, 32>>>();
    k_scan3<<<gScan, 1024>>>();
    k_scatter<<<(ET * N_EDGES + 255) / 256, 256>>>(edges);

    // layer 0: aggregate msgs -> agg planes; batched dual GEMM -> per-type norm; sum+relu/3+LN -> h
    k_agg3<<<dim3(gWarp, 3), 256>>>(msg0, msg1, msg2);
    k_gemm<<<dim3(gMma, 3), 256, SMEM_GEMM_BYTES>>>(
        ah, al, xh, xl, xh, xl, xh, xl,
        3, 6, 0, 0, 2, NC, bl0, ln_g, ln_b, msg0, msg1, msg2, 1);
    k_relu_ln3<<<gWarp, 256>>>(msg0, msg1, msg2, ln_g, ln_b);

    // layer 1: h = LN(relu((Σ agg@Wl + h@ΣWr + Σb)/3)) + planes
    k_agg3<<<dim3(gWarp, 3), 256>>>(h, h, h);
    k_gemm<<<dim3(gMma, 1), 256, SMEM_GEMM_BYTES>>>(
        ah, al, ah + (size_t)NC, al + (size_t)NC, ah + 2 * (size_t)NC, al + 2 * (size_t)NC,
        hh, hl, 9, 10, 11, 15, 4, 0, bsum, ln_g + C, ln_b + C, h, 0, 0, 3);

    // layer 2: out = (Σ agg@Wl + h@ΣWr + Σb)/3
    k_agg3<<<dim3(gWarp, 3), 256>>>(h, h, h);
    k_gemm<<<dim3(gMma, 1), 256, SMEM_GEMM_BYTES>>>(
        ah, al, ah + (size_t)NC, al + (size_t)NC, ah + 2 * (size_t)NC, al + 2 * (size_t)NC,
        hh, hl, 12, 13, 14, 16, 4, 0, bsum + C, ln_g, ln_b, out, 0, 0, 2);
}

// round 13
// speedup vs baseline: 1.1326x; 1.0071x over previous
#include <cuda_runtime.h>
#include <cuda_bf16.h>
#include <cstdint>

#define N_NODES 100000
#define N_EDGES 500000
#define ET 3
#define C 128
#define NC (N_NODES * C)
#define LN_EPS 1e-5f
#define L2_EPS 1e-12f

// BK=16 stage geometry: plane = 128 rows x 24 halves (16 data + 8 pad)
#define P2 24
#define CH2 (128 * P2)             // halves per plane (3072)
#define CB2 (CH2 * 2)              // bytes per plane (6144)
#define STAGE_B (4 * CB2)          // bytes per stage (24576)
#define NSTAGE 4
#define SMEM_GEMM_BYTES (NSTAGE * STAGE_B)   // 98304; 2 CTAs/SM

// ---------------- scratch (static device globals; no allocation) ----------------
__device__ float g_msg0[NC];
__device__ float g_msg1[NC];
__device__ float g_msg2[NC];
__device__ float g_h[NC];
__device__ __align__(16) __nv_bfloat16 g_xh[NC];
__device__ __align__(16) __nv_bfloat16 g_xl[NC];
__device__ __align__(16) __nv_bfloat16 g_ah[3 * NC];   // agg planes hi
__device__ __align__(16) __nv_bfloat16 g_al[3 * NC];   // agg planes lo
__device__ __align__(16) __nv_bfloat16 g_hh[NC];       // h planes
__device__ __align__(16) __nv_bfloat16 g_hl[NC];
__device__ __align__(16) __nv_bfloat16 g_wth[17 * C * C];  // transposed+split weights [n][k]
__device__ __align__(16) __nv_bfloat16 g_wtl[17 * C * C];
__device__ float g_wsum[2 * C * C];
__device__ float g_bsum[2 * C];
__device__ float g_invdeg[ET * N_NODES];
__device__ int g_cnt[ET * N_NODES];
__device__ int g_cur[ET * N_NODES];
__device__ int g_rowptr[ET * (N_NODES + 1)];
__device__ int g_col[ET * N_EDGES];
__device__ int g_bofs[ET * 128];

// ---------------- helpers ----------------
__device__ __forceinline__ uint32_t smem_u32(const void* p) {
    uint32_t a;
    asm("{ .reg .u64 t; cvta.to.shared.u64 t, %1; cvt.u32.u64 %0, t; }" : "=r"(a) : "l"(p));
    return a;
}
__device__ __forceinline__ void cp16(uint32_t dst, const void* src, int srcsize) {
    asm volatile("cp.async.cg.shared.global [%0], [%1], 16, %2;"
                 :: "r"(dst), "l"(src), "r"(srcsize));
}
#define CP_COMMIT() asm volatile("cp.async.commit_group;" ::: "memory")
#define CP_WAIT2()  asm volatile("cp.async.wait_group 2;" ::: "memory")

__device__ __forceinline__ void split2(float x, __nv_bfloat16& hi, __nv_bfloat16& lo) {
    hi = __float2bfloat16_rn(x);
    lo = __float2bfloat16_rn(x - __bfloat162float(hi));
}
__device__ __forceinline__ void mma_bf16(float* d, const uint32_t* a, uint32_t b0, uint32_t b1) {
    asm volatile(
        "mma.sync.aligned.m16n8k16.row.col.f32.bf16.bf16.f32 "
        "{%0,%1,%2,%3}, {%4,%5,%6,%7}, {%8,%9}, {%0,%1,%2,%3};"
        : "+f"(d[0]), "+f"(d[1]), "+f"(d[2]), "+f"(d[3])
        : "r"(a[0]), "r"(a[1]), "r"(a[2]), "r"(a[3]), "r"(b0), "r"(b1));
}
__device__ __forceinline__ void ldsm4(uint32_t a, uint32_t& r0, uint32_t& r1,
                                      uint32_t& r2, uint32_t& r3) {
    asm volatile("ldmatrix.sync.aligned.m8n8.x4.shared.b16 {%0,%1,%2,%3}, [%4];"
                 : "=r"(r0), "=r"(r1), "=r"(r2), "=r"(r3) : "r"(a));
}

// ---------------- CSR build ----------------
__global__ void k_zero_int() {
    int i = blockIdx.x * blockDim.x + threadIdx.x;
    if (i < ET * N_NODES) { g_cnt[i] = 0; g_cur[i] = 0; }
}
__global__ void k_hist(const int* __restrict__ edges) {
    int i = blockIdx.x * blockDim.x + threadIdx.x;
    if (i >= ET * N_EDGES) return;
    int t = i / N_EDGES, e = i - t * N_EDGES;
    int dst = edges[(t * 2 + 1) * N_EDGES + e];
    atomicAdd(&g_cnt[t * N_NODES + dst], 1);
}
__global__ void k_scan1() {
    int t = blockIdx.y;
    int i = blockIdx.x * 1024 + threadIdx.x;
    __shared__ int sm[1024];
    int v = (i < N_NODES) ? g_cnt[t * N_NODES + i] : 0;
    if (i < N_NODES)
        g_invdeg[t * N_NODES + i] = 1.0f / (float)(v > 1 ? v : 1);   // fused invdeg
    sm[threadIdx.x] = v;
    __syncthreads();
    for (int off = 1; off < 1024; off <<= 1) {
        int add = (threadIdx.x >= off) ? sm[threadIdx.x - off] : 0;
        __syncthreads();
        sm[threadIdx.x] += add;
        __syncthreads();
    }
    if (i < N_NODES) g_rowptr[t * (N_NODES + 1) + i] = sm[threadIdx.x] - v;
    if (threadIdx.x == 1023) g_bofs[t * 128 + blockIdx.x] = sm[1023];
}
__global__ void k_scan2() {
    int t = threadIdx.x;
    if (t >= ET) return;
    int nb = (N_NODES + 1023) / 1024;
    int run = 0;
    for (int b = 0; b < nb; b++) { int v = g_bofs[t * 128 + b]; g_bofs[t * 128 + b] = run; run += v; }
    g_rowptr[t * (N_NODES + 1) + N_NODES] = run;
}
__global__ void k_scan3() {
    int t = blockIdx.y;
    int i = blockIdx.x * 1024 + threadIdx.x;
    if (i < N_NODES) g_rowptr[t * (N_NODES + 1) + i] += g_bofs[t * 128 + blockIdx.x];
}
__global__ void k_scatter(const int* __restrict__ edges) {
    int i = blockIdx.x * blockDim.x + threadIdx.x;
    if (i >= ET * N_EDGES) return;
    int t = i / N_EDGES, e = i - t * N_EDGES;
    int src = edges[t * 2 * N_EDGES + e];
    int dst = edges[(t * 2 + 1) * N_EDGES + e];
    int pos = g_rowptr[t * (N_NODES + 1) + dst] + atomicAdd(&g_cur[t * N_NODES + dst], 1);
    g_col[t * N_EDGES + pos] = src;
}

// ---------------- weight pre-sum + prep ----------------
__global__ void k_wsum(const float* __restrict__ Wr, const float* __restrict__ bl) {
    int i = blockIdx.x * blockDim.x + threadIdx.x;
    if (i < 2 * C * C) {
        int l = i / (C * C), idx = i - l * (C * C);
        g_wsum[i] = Wr[(l * 3 + 0) * C * C + idx] + Wr[(l * 3 + 1) * C * C + idx]
                  + Wr[(l * 3 + 2) * C * C + idx];
    }
    if (i < 2 * C) {
        int l = i / C, cc = i - l * C;
        g_bsum[i] = bl[(l * 3 + 0) * C + cc] + bl[(l * 3 + 1) * C + cc] + bl[(l * 3 + 2) * C + cc];
    }
}
// mats: 0-2 Wp, 3-5 Wl0, 6-8 Wr0, 9-14 Wl, 15-16 wsum.  out[m][n][k] = split(W[m][k][n])
__global__ void k_wprep(const float* __restrict__ Wp, const float* __restrict__ Wl0,
                        const float* __restrict__ Wr0, const float* __restrict__ Wl) {
    int m = blockIdx.y;
    const float* src;
    if (m < 3) src = Wp + (size_t)m * C * C;
    else if (m < 6) src = Wl0 + (size_t)(m - 3) * C * C;
    else if (m < 9) src = Wr0 + (size_t)(m - 6) * C * C;
    else if (m < 15) src = Wl + (size_t)(m - 9) * C * C;
    else src = g_wsum + (size_t)(m - 15) * C * C;
    __shared__ float tile[32][33];
    int txt = (blockIdx.x & 3) * 32, tyt = (blockIdx.x >> 2) * 32;
    int tx = threadIdx.x, ty = threadIdx.y;
    #pragma unroll
    for (int i = 0; i < 4; i++)
        tile[ty + i * 8][tx] = src[(size_t)(tyt + ty + i * 8) * C + txt + tx];
    __syncthreads();
    #pragma unroll
    for (int i = 0; i < 4; i++) {
        int n = txt + ty + i * 8, k = tyt + tx;
        float v = tile[tx][ty + i * 8];
        __nv_bfloat16 hi, lo; split2(v, hi, lo);
        g_wth[(size_t)m * C * C + n * C + k] = hi;
        g_wtl[(size_t)m * C * C + n * C + k] = lo;
    }
}
// split x once into bf16 planes
__global__ void k_xprep(const float* __restrict__ x) {
    int i = blockIdx.x * blockDim.x + threadIdx.x;
    if (i * 4 >= NC) return;
    float4 v = *reinterpret_cast<const float4*>(&x[(size_t)i * 4]);
    __nv_bfloat162 hA, hB, lA, lB;
    split2(v.x, hA.x, lA.x); split2(v.y, hA.y, lA.y);
    split2(v.z, hB.x, lB.x); split2(v.w, hB.y, lB.y);
    uint2 uh, ul;
    uh.x = *reinterpret_cast<uint32_t*>(&hA); uh.y = *reinterpret_cast<uint32_t*>(&hB);
    ul.x = *reinterpret_cast<uint32_t*>(&lA); ul.y = *reinterpret_cast<uint32_t*>(&lB);
    *reinterpret_cast<uint2*>(&g_xh[(size_t)i * 4]) = uh;
    *reinterpret_cast<uint2*>(&g_xl[(size_t)i * 4]) = ul;
}

// ---------------- mean aggregation: grid.y = edge type (3x warp parallelism) ----------------
__global__ void k_agg3(const float* __restrict__ f0, const float* __restrict__ f1,
                       const float* __restrict__ f2) {
    int t = blockIdx.y;
    int w = (blockIdx.x * blockDim.x + threadIdx.x) >> 5;
    int lane = threadIdx.x & 31;
    if (w >= N_NODES) return;
    const float* feat = (t == 0) ? f0 : (t == 1) ? f1 : f2;
    const int* rp = &g_rowptr[t * (N_NODES + 1)];
    int s = rp[w], e = rp[w + 1];
    const int* col = &g_col[t * N_EDGES];
    float4 acc = make_float4(0.f, 0.f, 0.f, 0.f);
    int j = s;
    for (; j + 3 < e; j += 4) {
        int s0 = col[j], s1 = col[j + 1], s2 = col[j + 2], s3 = col[j + 3];
        float4 v0 = *reinterpret_cast<const float4*>(&feat[(size_t)s0 * C + lane * 4]);
        float4 v1 = *reinterpret_cast<const float4*>(&feat[(size_t)s1 * C + lane * 4]);
        float4 v2 = *reinterpret_cast<const float4*>(&feat[(size_t)s2 * C + lane * 4]);
        float4 v3 = *reinterpret_cast<const float4*>(&feat[(size_t)s3 * C + lane * 4]);
        acc.x += v0.x; acc.y += v0.y; acc.z += v0.z; acc.w += v0.w;
        acc.x += v1.x; acc.y += v1.y; acc.z += v1.z; acc.w += v1.w;
        acc.x += v2.x; acc.y += v2.y; acc.z += v2.z; acc.w += v2.w;
        acc.x += v3.x; acc.y += v3.y; acc.z += v3.z; acc.w += v3.w;
    }
    for (; j < e; j++) {
        int s0 = col[j];
        float4 v0 = *reinterpret_cast<const float4*>(&feat[(size_t)s0 * C + lane * 4]);
        acc.x += v0.x; acc.y += v0.y; acc.z += v0.z; acc.w += v0.w;
    }
    float inv = g_invdeg[t * N_NODES + w];
    acc.x *= inv; acc.y *= inv; acc.z *= inv; acc.w *= inv;
    __nv_bfloat162 hA, hB, lA, lB;
    split2(acc.x, hA.x, lA.x); split2(acc.y, hA.y, lA.y);
    split2(acc.z, hB.x, lB.x); split2(acc.w, hB.y, lB.y);
    size_t off = (size_t)t * NC + (size_t)w * C + lane * 4;
    uint2 uh, ul;
    uh.x = *reinterpret_cast<uint32_t*>(&hA); uh.y = *reinterpret_cast<uint32_t*>(&hB);
    ul.x = *reinterpret_cast<uint32_t*>(&lA); ul.y = *reinterpret_cast<uint32_t*>(&lB);
    *reinterpret_cast<uint2*>(&g_ah[off]) = uh;
    *reinterpret_cast<uint2*>(&g_al[off]) = ul;
}

// ---------------- sum3 + relu/3 + LayerNorm -> h fp32 + planes ----------------
__global__ void k_relu_ln3(const float* __restrict__ i0, const float* __restrict__ i1,
                           const float* __restrict__ i2,
                           const float* __restrict__ g, const float* __restrict__ b) {
    int w = (blockIdx.x * blockDim.x + threadIdx.x) >> 5;
    int lane = threadIdx.x & 31;
    if (w >= N_NODES) return;
    size_t off0 = (size_t)w * C + lane * 4;
    float4 a0 = *reinterpret_cast<const float4*>(&i0[off0]);
    float4 a1 = *reinterpret_cast<const float4*>(&i1[off0]);
    float4 a2 = *reinterpret_cast<const float4*>(&i2[off0]);
    float4 v;
    v.x = (a0.x + a1.x) + a2.x;
    v.y = (a0.y + a1.y) + a2.y;
    v.z = (a0.z + a1.z) + a2.z;
    v.w = (a0.w + a1.w) + a2.w;
    v.x = fmaxf(v.x * (1.f / 3.f), 0.f);
    v.y = fmaxf(v.y * (1.f / 3.f), 0.f);
    v.z = fmaxf(v.z * (1.f / 3.f), 0.f);
    v.w = fmaxf(v.w * (1.f / 3.f), 0.f);
    float s = v.x + v.y + v.z + v.w;
    #pragma unroll
    for (int off = 16; off > 0; off >>= 1) s += __shfl_xor_sync(0xffffffffu, s, off);
    float mean = s * (1.f / 128.f);
    float dx = v.x - mean, dy = v.y - mean, dz = v.z - mean, dw = v.w - mean;
    float ss = dx * dx + dy * dy + dz * dz + dw * dw;
    #pragma unroll
    for (int off = 16; off > 0; off >>= 1) ss += __shfl_xor_sync(0xffffffffu, ss, off);
    float rstd = rsqrtf(ss * (1.f / 128.f) + LN_EPS);
    float4 gg = *reinterpret_cast<const float4*>(&g[lane * 4]);
    float4 bb = *reinterpret_cast<const float4*>(&b[lane * 4]);
    float4 o;
    o.x = dx * rstd * gg.x + bb.x;
    o.y = dy * rstd * gg.y + bb.y;
    o.z = dz * rstd * gg.z + bb.z;
    o.w = dw * rstd * gg.w + bb.w;
    *reinterpret_cast<float4*>(&g_h[off0]) = o;
    __nv_bfloat162 hA, hB, lA, lB;
    split2(o.x, hA.x, lA.x); split2(o.y, hA.y, lA.y);
    split2(o.z, hB.x, lB.x); split2(o.w, hB.y, lB.y);
    uint2 uh, ul;
    uh.x = *reinterpret_cast<uint32_t*>(&hA); uh.y = *reinterpret_cast<uint32_t*>(&hB);
    ul.x = *reinterpret_cast<uint32_t*>(&lA); ul.y = *reinterpret_cast<uint32_t*>(&lB);
    *reinterpret_cast<uint2*>(&g_hh[off0]) = uh;
    *reinterpret_cast<uint2*>(&g_hl[off0]) = ul;
}

// ---------------- one 128x128x16 stage: ldmatrix + dependency-spread passes ----------------
__device__ __forceinline__ void mma_stage16(
    uint32_t Ahi, uint32_t Alo, uint32_t Bhi, uint32_t Blo,
    int wm, int wn, int lane, float (*acc)[8][4])
{
    int aRow = lane & 15;
    uint32_t aColB = ((lane >> 4) & 1) * 16;
    int bRow = (lane & 7) | (((lane >> 4) & 1) << 3);
    uint32_t bColB = ((lane >> 3) & 1) * 16;
    uint32_t aoff0 = (uint32_t)((wm * 32 + aRow) * 48) + aColB;
    uint32_t aoff1 = aoff0 + 16 * 48;
    uint32_t boff = (uint32_t)((wn * 64 + bRow) * 48) + bColB;
    uint32_t ah[2][4], al[2][4];
    ldsm4(Ahi + aoff0, ah[0][0], ah[0][1], ah[0][2], ah[0][3]);
    ldsm4(Ahi + aoff1, ah[1][0], ah[1][1], ah[1][2], ah[1][3]);
    ldsm4(Alo + aoff0, al[0][0], al[0][1], al[0][2], al[0][3]);
    ldsm4(Alo + aoff1, al[1][0], al[1][1], al[1][2], al[1][3]);
    #pragma unroll
    for (int q = 0; q < 2; q++) {
        uint32_t nq = boff + (uint32_t)(q * 32 * 48);
        uint32_t bh[4][2], bl[4][2];
        ldsm4(Bhi + nq,           bh[0][0], bh[0][1], bh[1][0], bh[1][1]);
        ldsm4(Bhi + nq + 16 * 48, bh[2][0], bh[2][1], bh[3][0], bh[3][1]);
        ldsm4(Blo + nq,           bl[0][0], bl[0][1], bl[1][0], bl[1][1]);
        ldsm4(Blo + nq + 16 * 48, bl[2][0], bl[2][1], bl[3][0], bl[3][1]);
        #pragma unroll
        for (int j = 0; j < 4; j++) {
            mma_bf16(acc[0][q * 4 + j], ah[0], bh[j][0], bh[j][1]);
            mma_bf16(acc[1][q * 4 + j], ah[1], bh[j][0], bh[j][1]);
        }
        #pragma unroll
        for (int j = 0; j < 4; j++) {
            mma_bf16(acc[0][q * 4 + j], ah[0], bl[j][0], bl[j][1]);
            mma_bf16(acc[1][q * 4 + j], ah[1], bl[j][0], bl[j][1]);
        }
        #pragma unroll
        for (int j = 0; j < 4; j++) {
            mma_bf16(acc[0][q * 4 + j], al[0], bh[j][0], bh[j][1]);
            mma_bf16(acc[1][q * 4 + j], al[1], bh[j][0], bh[j][1]);
        }
    }
}

// ---------------- unified streaming GEMM (cp.async 4-deep ring, 1 sync/stage) ----------------
// batched over blockIdx.y = tt: mats += tt, bias += tt*C, A chunk0 += tt*aStride0,
// out = {o0,o1,o2}[tt].  Epilogue by mode:
//  0: out = relu(acc+bias)
//  1: out = L2rownorm(acc+bias)           (write, no RMW)
//  2: out = (acc+bias)/3
//  3: out = LN(relu((acc+bias)/3)) + write g_hh/g_hl planes
__global__ __launch_bounds__(256, 2) void k_gemm(
    const __nv_bfloat16* __restrict__ A0h, const __nv_bfloat16* __restrict__ A0l,
    const __nv_bfloat16* __restrict__ A1h, const __nv_bfloat16* __restrict__ A1l,
    const __nv_bfloat16* __restrict__ A2h, const __nv_bfloat16* __restrict__ A2l,
    const __nv_bfloat16* __restrict__ A3h, const __nv_bfloat16* __restrict__ A3l,
    int m0, int m1, int m2, int m3, int nChunks, int aStride0,
    const float* __restrict__ bias, const float* __restrict__ lng,
    const float* __restrict__ lnb,
    float* __restrict__ o0, float* __restrict__ o1, float* __restrict__ o2, int mode)
{
    extern __shared__ __align__(16) char smem[];
    uint32_t sb = smem_u32(smem);
    int tt = blockIdx.y;
    int t = threadIdx.x, lane = t & 31, wid = t >> 5;
    int g = lane >> 2, tg = lane & 3;
    int wm = wid & 3, wn = wid >> 2;
    int row0 = blockIdx.x * 128;
    int ar = t >> 1, sel = t & 1;
    uint32_t soff = (uint32_t)(ar * 48 + sel * 16);
    int gr = row0 + ar;
    bool rvalid = gr < N_NODES;
    int grc = rvalid ? gr : (N_NODES - 1);
    int ssz = rvalid ? 16 : 0;

    const __nv_bfloat16* Ah[4] = {A0h + (size_t)tt * aStride0, A1h, A2h, A3h};
    const __nv_bfloat16* Al[4] = {A0l + (size_t)tt * aStride0, A1l, A2l, A3l};
    int mats[4] = {m0 + tt, m1 + tt, m2 + tt, m3 + tt};
    bias += tt * C;
    float* outf = (tt == 0) ? o0 : (tt == 1) ? o1 : o2;
    int nStages = nChunks * 8;     // K chunks of 16

    auto issue = [&](int s) {
        if (s < nStages) {
            uint32_t slot = sb + (uint32_t)(s & (NSTAGE - 1)) * STAGE_B;
            int c = s >> 3, kc = (s & 7) * 16;
            size_t ae = (size_t)grc * C + kc + sel * 8;
            cp16(slot + soff, Ah[c] + ae, ssz);
            cp16(slot + CB2 + soff, Al[c] + ae, ssz);
            size_t be = (size_t)mats[c] * C * C + (size_t)ar * C + kc + sel * 8;
            cp16(slot + 2 * CB2 + soff, g_wth + be, 16);
            cp16(slot + 3 * CB2 + soff, g_wtl + be, 16);
        }
        CP_COMMIT();
    };

    float acc[2][8][4];
    #pragma unroll
    for (int mi = 0; mi < 2; mi++)
        #pragma unroll
        for (int ni = 0; ni < 8; ni++)
            #pragma unroll
            for (int r = 0; r < 4; r++) acc[mi][ni][r] = 0.f;

    issue(0); issue(1); issue(2);
    for (int s = 0; s < nStages; s++) {
        CP_WAIT2();
        __syncthreads();
        issue(s + 3);
        uint32_t slot = sb + (uint32_t)(s & (NSTAGE - 1)) * STAGE_B;
        mma_stage16(slot, slot + CB2, slot + 2 * CB2, slot + 3 * CB2, wm, wn, lane, acc);
    }
    __syncthreads();

    // ---- epilogues ----
    if (mode == 0) {
        #pragma unroll
        for (int mi = 0; mi < 2; mi++) {
            int r0 = row0 + wm * 32 + mi * 16 + g, r1 = r0 + 8;
            #pragma unroll
            for (int ni = 0; ni < 8; ni++) {
                int coln = wn * 64 + ni * 8 + tg * 2;
                float2 bv = *reinterpret_cast<const float2*>(&bias[coln]);
                float2 u0, u1;
                u0.x = fmaxf(acc[mi][ni][0] + bv.x, 0.f);
                u0.y = fmaxf(acc[mi][ni][1] + bv.y, 0.f);
                u1.x = fmaxf(acc[mi][ni][2] + bv.x, 0.f);
                u1.y = fmaxf(acc[mi][ni][3] + bv.y, 0.f);
                if (r0 < N_NODES) *reinterpret_cast<float2*>(&outf[(size_t)r0 * C + coln]) = u0;
                if (r1 < N_NODES) *reinterpret_cast<float2*>(&outf[(size_t)r1 * C + coln]) = u1;
            }
        }
        return;
    }

    if (mode == 1) {
        #pragma unroll
        for (int ni = 0; ni < 8; ni++) {
            int coln = wn * 64 + ni * 8 + tg * 2;
            float2 bv = *reinterpret_cast<const float2*>(&bias[coln]);
            #pragma unroll
            for (int mi = 0; mi < 2; mi++) {
                acc[mi][ni][0] += bv.x; acc[mi][ni][1] += bv.y;
                acc[mi][ni][2] += bv.x; acc[mi][ni][3] += bv.y;
            }
        }
        float* red = (float*)smem;       // [128][2]
        float* invn = red + 256;         // [128]
        float ss0[2] = {0.f, 0.f}, ss1[2] = {0.f, 0.f};
        #pragma unroll
        for (int mi = 0; mi < 2; mi++)
            #pragma unroll
            for (int ni = 0; ni < 8; ni++) {
                ss0[mi] += acc[mi][ni][0] * acc[mi][ni][0] + acc[mi][ni][1] * acc[mi][ni][1];
                ss1[mi] += acc[mi][ni][2] * acc[mi][ni][2] + acc[mi][ni][3] * acc[mi][ni][3];
            }
        #pragma unroll
        for (int mi = 0; mi < 2; mi++) {
            ss0[mi] += __shfl_xor_sync(0xffffffffu, ss0[mi], 1);
            ss0[mi] += __shfl_xor_sync(0xffffffffu, ss0[mi], 2);
            ss1[mi] += __shfl_xor_sync(0xffffffffu, ss1[mi], 1);
            ss1[mi] += __shfl_xor_sync(0xffffffffu, ss1[mi], 2);
        }
        if (tg == 0) {
            #pragma unroll
            for (int mi = 0; mi < 2; mi++) {
                red[(wm * 32 + mi * 16 + g) * 2 + wn] = ss0[mi];
                red[(wm * 32 + mi * 16 + 8 + g) * 2 + wn] = ss1[mi];
            }
        }
        __syncthreads();
        if (t < 128) invn[t] = 1.f / fmaxf(sqrtf(red[t * 2] + red[t * 2 + 1]), L2_EPS);
        __syncthreads();
        #pragma unroll
        for (int mi = 0; mi < 2; mi++) {
            int lr0 = wm * 32 + mi * 16 + g;
            int r0 = row0 + lr0, r1 = r0 + 8;
            float i0 = invn[lr0], i1 = invn[lr0 + 8];
            #pragma unroll
            for (int ni = 0; ni < 8; ni++) {
                int coln = wn * 64 + ni * 8 + tg * 2;
                if (r0 < N_NODES) {
                    float2 o;
                    o.x = acc[mi][ni][0] * i0;
                    o.y = acc[mi][ni][1] * i0;
                    *reinterpret_cast<float2*>(&outf[(size_t)r0 * C + coln]) = o;
                }
                if (r1 < N_NODES) {
                    float2 o;
                    o.x = acc[mi][ni][2] * i1;
                    o.y = acc[mi][ni][3] * i1;
                    *reinterpret_cast<float2*>(&outf[(size_t)r1 * C + coln]) = o;
                }
            }
        }
        return;
    }

    const float sc = 1.f / 3.f;
    #pragma unroll
    for (int ni = 0; ni < 8; ni++) {
        int coln = wn * 64 + ni * 8 + tg * 2;
        float2 bv = *reinterpret_cast<const float2*>(&bias[coln]);
        #pragma unroll
        for (int mi = 0; mi < 2; mi++) {
            acc[mi][ni][0] = (acc[mi][ni][0] + bv.x) * sc;
            acc[mi][ni][1] = (acc[mi][ni][1] + bv.y) * sc;
            acc[mi][ni][2] = (acc[mi][ni][2] + bv.x) * sc;
            acc[mi][ni][3] = (acc[mi][ni][3] + bv.y) * sc;
            if (mode == 3) {
                acc[mi][ni][0] = fmaxf(acc[mi][ni][0], 0.f);
                acc[mi][ni][1] = fmaxf(acc[mi][ni][1], 0.f);
                acc[mi][ni][2] = fmaxf(acc[mi][ni][2], 0.f);
                acc[mi][ni][3] = fmaxf(acc[mi][ni][3], 0.f);
            }
        }
    }

    if (mode == 2) {
        #pragma unroll
        for (int mi = 0; mi < 2; mi++) {
            int r0 = row0 + wm * 32 + mi * 16 + g, r1 = r0 + 8;
            #pragma unroll
            for (int ni = 0; ni < 8; ni++) {
                int coln = wn * 64 + ni * 8 + tg * 2;
                if (r0 < N_NODES) {
                    float2 o; o.x = acc[mi][ni][0]; o.y = acc[mi][ni][1];
                    *reinterpret_cast<float2*>(&outf[(size_t)r0 * C + coln]) = o;
                }
                if (r1 < N_NODES) {
                    float2 o; o.x = acc[mi][ni][2]; o.y = acc[mi][ni][3];
                    *reinterpret_cast<float2*>(&outf[(size_t)r1 * C + coln]) = o;
                }
            }
        }
        return;
    }

    // mode 3: fused LayerNorm + h planes
    {
        float* red_s = (float*)smem;     // [128][2]
        float* red_q = red_s + 256;      // [128][2]
        float* rmean = red_q + 256;      // [128]
        float* rstdv = rmean + 128;      // [128]
        float s0[2] = {0.f, 0.f}, q0[2] = {0.f, 0.f};
        float s1[2] = {0.f, 0.f}, q1[2] = {0.f, 0.f};
        #pragma unroll
        for (int mi = 0; mi < 2; mi++)
            #pragma unroll
            for (int ni = 0; ni < 8; ni++) {
                s0[mi] += acc[mi][ni][0] + acc[mi][ni][1];
                q0[mi] += acc[mi][ni][0] * acc[mi][ni][0] + acc[mi][ni][1] * acc[mi][ni][1];
                s1[mi] += acc[mi][ni][2] + acc[mi][ni][3];
                q1[mi] += acc[mi][ni][2] * acc[mi][ni][2] + acc[mi][ni][3] * acc[mi][ni][3];
            }
        #pragma unroll
        for (int mi = 0; mi < 2; mi++) {
            s0[mi] += __shfl_xor_sync(0xffffffffu, s0[mi], 1);
            s0[mi] += __shfl_xor_sync(0xffffffffu, s0[mi], 2);
            q0[mi] += __shfl_xor_sync(0xffffffffu, q0[mi], 1);
            q0[mi] += __shfl_xor_sync(0xffffffffu, q0[mi], 2);
            s1[mi] += __shfl_xor_sync(0xffffffffu, s1[mi], 1);
            s1[mi] += __shfl_xor_sync(0xffffffffu, s1[mi], 2);
            q1[mi] += __shfl_xor_sync(0xffffffffu, q1[mi], 1);
            q1[mi] += __shfl_xor_sync(0xffffffffu, q1[mi], 2);
        }
        if (tg == 0) {
            #pragma unroll
            for (int mi = 0; mi < 2; mi++) {
                int lr = wm * 32 + mi * 16 + g;
                red_s[lr * 2 + wn] = s0[mi];
                red_q[lr * 2 + wn] = q0[mi];
                red_s[(lr + 8) * 2 + wn] = s1[mi];
                red_q[(lr + 8) * 2 + wn] = q1[mi];
            }
        }
        __syncthreads();
        if (t < 128) {
            float ssum = red_s[t * 2] + red_s[t * 2 + 1];
            float qsum = red_q[t * 2] + red_q[t * 2 + 1];
            float mean = ssum * (1.f / 128.f);
            float var = qsum * (1.f / 128.f) - mean * mean;
            rmean[t] = mean;
            rstdv[t] = rsqrtf(fmaxf(var, 0.f) + LN_EPS);
        }
        __syncthreads();
        #pragma unroll
        for (int mi = 0; mi < 2; mi++) {
            int lr0 = wm * 32 + mi * 16 + g;
            int r0 = row0 + lr0, r1 = r0 + 8;
            float m0v = rmean[lr0], d0 = rstdv[lr0];
            float m1v = rmean[lr0 + 8], d1 = rstdv[lr0 + 8];
            #pragma unroll
            for (int ni = 0; ni < 8; ni++) {
                int coln = wn * 64 + ni * 8 + tg * 2;
                float2 gv = *reinterpret_cast<const float2*>(&lng[coln]);
                float2 bb = *reinterpret_cast<const float2*>(&lnb[coln]);
                if (r0 < N_NODES) {
                    float2 o;
                    o.x = (acc[mi][ni][0] - m0v) * d0 * gv.x + bb.x;
                    o.y = (acc[mi][ni][1] - m0v) * d0 * gv.y + bb.y;
                    *reinterpret_cast<float2*>(&outf[(size_t)r0 * C + coln]) = o;
                    __nv_bfloat162 hh, ll;
                    split2(o.x, hh.x, ll.x); split2(o.y, hh.y, ll.y);
                    *reinterpret_cast<__nv_bfloat162*>(&g_hh[(size_t)r0 * C + coln]) = hh;
                    *reinterpret_cast<__nv_bfloat162*>(&g_hl[(size_t)r0 * C + coln]) = ll;
                }
                if (r1 < N_NODES) {
                    float2 o;
                    o.x = (acc[mi][ni][2] - m1v) * d1 * gv.x + bb.x;
                    o.y = (acc[mi][ni][3] - m1v) * d1 * gv.y + bb.y;
                    *reinterpret_cast<float2*>(&outf[(size_t)r1 * C + coln]) = o;
                    __nv_bfloat162 hh, ll;
                    split2(o.x, hh.x, ll.x); split2(o.y, hh.y, ll.y);
                    *reinterpret_cast<__nv_bfloat162*>(&g_hh[(size_t)r1 * C + coln]) = hh;
                    *reinterpret_cast<__nv_bfloat162*>(&g_hl[(size_t)r1 * C + coln]) = ll;
                }
            }
        }
    }
}

// ---------------- host orchestration (CSR build forked onto side stream) ----------------
static cudaStream_t g_side = nullptr;
static cudaEvent_t g_evFork = nullptr;
static cudaEvent_t g_evJoin = nullptr;

extern "C" void kernel_launch(void* const* d_in, const int* in_sizes, int n_in,
                              void* d_out, int out_size) {
    const float* x    = (const float*)d_in[0];
    const int*   edges = (const int*)d_in[1];
    const float* Wp   = (const float*)d_in[2];
    const float* bp   = (const float*)d_in[3];
    const float* Wl0  = (const float*)d_in[4];
    const float* bl0  = (const float*)d_in[5];
    const float* Wr0  = (const float*)d_in[6];
    const float* Wl   = (const float*)d_in[7];
    const float* bl   = (const float*)d_in[8];
    const float* Wr   = (const float*)d_in[9];
    const float* ln_g = (const float*)d_in[10];
    const float* ln_b = (const float*)d_in[11];
    float* out = (float*)d_out;

    void* p;
    float *msg0, *msg1, *msg2, *h, *bsum;
    __nv_bfloat16 *xh, *xl, *ah, *al, *hh, *hl;
    cudaGetSymbolAddress(&p, g_msg0); msg0 = (float*)p;
    cudaGetSymbolAddress(&p, g_msg1); msg1 = (float*)p;
    cudaGetSymbolAddress(&p, g_msg2); msg2 = (float*)p;
    cudaGetSymbolAddress(&p, g_h);    h = (float*)p;
    cudaGetSymbolAddress(&p, g_bsum); bsum = (float*)p;
    cudaGetSymbolAddress(&p, g_xh);   xh = (__nv_bfloat16*)p;
    cudaGetSymbolAddress(&p, g_xl);   xl = (__nv_bfloat16*)p;
    cudaGetSymbolAddress(&p, g_ah);   ah = (__nv_bfloat16*)p;
    cudaGetSymbolAddress(&p, g_al);   al = (__nv_bfloat16*)p;
    cudaGetSymbolAddress(&p, g_hh);   hh = (__nv_bfloat16*)p;
    cudaGetSymbolAddress(&p, g_hl);   hl = (__nv_bfloat16*)p;

    cudaFuncSetAttribute(k_gemm, cudaFuncAttributeMaxDynamicSharedMemorySize, SMEM_GEMM_BYTES);

    // One-time resource setup (first call is the uncaptured correctness run;
    // every call issues the IDENTICAL launch/work sequence below).
    if (!g_side) {
        cudaStreamCreateWithFlags(&g_side, cudaStreamNonBlocking);
        cudaEventCreateWithFlags(&g_evFork, cudaEventDisableTiming);
        cudaEventCreateWithFlags(&g_evJoin, cudaEventDisableTiming);
    }

    int nbScan = (N_NODES + 1023) / 1024;
    dim3 gScan(nbScan, ET);
    int gMma = (N_NODES + 127) / 128;
    int gWarp = (N_NODES * 32 + 255) / 256;

    // ---- fork: CSR build on side stream, prep+proj on main stream ----
    cudaEventRecord(g_evFork, 0);
    cudaStreamWaitEvent(g_side, g_evFork, 0);

    // side stream: full CSR build (independent of weights/x prep and proj GEMM)
    k_zero_int<<<(ET * N_NODES + 255) / 256, 256, 0, g_side>>>();
    k_hist<<<(ET * N_EDGES + 255) / 256, 256, 0, g_side>>>(edges);
    k_scan1<<<gScan, 1024, 0, g_side>>>();
    k_scan2<<<1, 32, 0, g_side>>>();
    k_scan3<<<gScan, 1024, 0, g_side>>>();
    k_scatter<<<(ET * N_EDGES + 255) / 256, 256, 0, g_side>>>(edges);
    cudaEventRecord(g_evJoin, g_side);

    // main stream: weight + x prep, then all three projections in one batched launch
    k_wsum<<<(2 * C * C + 255) / 256, 256>>>(Wr, bl);
    k_wprep<<<dim3(16, 17), dim3(32, 8)>>>(Wp, Wl0, Wr0, Wl);
    k_xprep<<<(NC / 4 + 255) / 256, 256>>>(x);
    k_gemm<<<dim3(gMma, 3), 256, SMEM_GEMM_BYTES>>>(
        xh, xl, xh, xl, xh, xl, xh, xl,
        0, 0, 0, 0, 1, 0, bp, ln_g, ln_b, msg0, msg1, msg2, 0);

    // join: aggregation needs both CSR and msgs
    cudaStreamWaitEvent(0, g_evJoin, 0);

    // layer 0: aggregate msgs -> agg planes; batched dual GEMM -> per-type norm; sum+relu/3+LN -> h
    k_agg3<<<dim3(gWarp, 3), 256>>>(msg0, msg1, msg2);
    k_gemm<<<dim3(gMma, 3), 256, SMEM_GEMM_BYTES>>>(
        ah, al, xh, xl, xh, xl, xh, xl,
        3, 6, 0, 0, 2, NC, bl0, ln_g, ln_b, msg0, msg1, msg2, 1);
    k_relu_ln3<<<gWarp, 256>>>(msg0, msg1, msg2, ln_g, ln_b);

    // layer 1: h = LN(relu((Σ agg@Wl + h@ΣWr + Σb)/3)) + planes
    k_agg3<<<dim3(gWarp, 3), 256>>>(h, h, h);
    k_gemm<<<dim3(gMma, 1), 256, SMEM_GEMM_BYTES>>>(
        ah, al, ah + (size_t)NC, al + (size_t)NC, ah + 2 * (size_t)NC, al + 2 * (size_t)NC,
        hh, hl, 9, 10, 11, 15, 4, 0, bsum, ln_g + C, ln_b + C, h, 0, 0, 3);

    // layer 2: out = (Σ agg@Wl + h@ΣWr + Σb)/3
    k_agg3<<<dim3(gWarp, 3), 256>>>(h, h, h);
    k_gemm<<<dim3(gMma, 1), 256, SMEM_GEMM_BYTES>>>(
        ah, al, ah + (size_t)NC, al + (size_t)NC, ah + 2 * (size_t)NC, al + 2 * (size_t)NC,
        hh, hl, 12, 13, 14, 16, 4, 0, bsum + C, ln_g, ln_b, out, 0, 0, 2);
}